// round 10
// baseline (speedup 1.0000x reference)
#include <cuda_runtime.h>
#include <cstdint>

#define NV 4096
#define ALPHA 0.2f

// ---------------- device scratch ----------------
__device__ float g_Wh[NV * 64];
__device__ float g_e1[NV], g_e2[NV];
__device__ float g_E1[NV], g_E2[NV];
__device__ float g_A[NV], g_B[NV], g_thE[NV], g_dinv[NV];
__device__ float g_part[16][NV * 64];
__device__ uint2 g_WhC[64 * (NV / 2)];        // [c][j/2] = {bf16x2 hi, bf16x2 lo}
__device__ unsigned g_bits[NV * (NV / 32)];   // adjacency bitmask [i][j/32]

// ---------------- K1: Wh = H@W + e1/e2 + E1/E2 ----------------
__global__ __launch_bounds__(256) void k1_wh(const float* __restrict__ H,
                                             const float* __restrict__ W,
                                             const float* __restrict__ a) {
    __shared__ float Hs[16][68];
    __shared__ float Ws[64][64];
    int tid = threadIdx.x;
    int tr = tid >> 4;
    int tc = tid & 15;
    int row0 = blockIdx.x * 16;

    unsigned long long acc[2] = {0ull, 0ull};

    for (int kk = 0; kk < 256; kk += 64) {
#pragma unroll
        for (int t = 0; t < 4; t++) {
            int u = tid + t * 256;
            int r = u >> 4, c4 = u & 15;
            *(float4*)&Ws[r][c4 * 4] = *(const float4*)&W[(size_t)(kk + r) * 64 + c4 * 4];
        }
        *(float4*)&Hs[tr][tc * 4] = *(const float4*)&H[(size_t)(row0 + tr) * 256 + kk + tc * 4];
        __syncthreads();
#pragma unroll 8
        for (int k = 0; k < 64; k++) {
            float4 w4 = *(const float4*)&Ws[k][tc * 4];
            unsigned long long w01, w23, hp;
            asm("mov.b64 %0, {%1, %2};" : "=l"(w01) : "f"(w4.x), "f"(w4.y));
            asm("mov.b64 %0, {%1, %2};" : "=l"(w23) : "f"(w4.z), "f"(w4.w));
            float h = Hs[tr][k];
            asm("mov.b64 %0, {%1, %1};" : "=l"(hp) : "f"(h));
            asm("fma.rn.f32x2 %0, %1, %2, %0;" : "+l"(acc[0]) : "l"(hp), "l"(w01));
            asm("fma.rn.f32x2 %0, %1, %2, %0;" : "+l"(acc[1]) : "l"(hp), "l"(w23));
        }
        __syncthreads();
    }

    float v0 = __uint_as_float((uint32_t)acc[0]);
    float v1 = __uint_as_float((uint32_t)(acc[0] >> 32));
    float v2 = __uint_as_float((uint32_t)acc[1]);
    float v3 = __uint_as_float((uint32_t)(acc[1] >> 32));

    int i = row0 + tr;
    *(float4*)&g_Wh[(size_t)i * 64 + tc * 4] = make_float4(v0, v1, v2, v3);

    float p1 = v0 * __ldg(&a[tc * 4]) + v1 * __ldg(&a[tc * 4 + 1])
             + v2 * __ldg(&a[tc * 4 + 2]) + v3 * __ldg(&a[tc * 4 + 3]);
    float p2 = v0 * __ldg(&a[64 + tc * 4]) + v1 * __ldg(&a[64 + tc * 4 + 1])
             + v2 * __ldg(&a[64 + tc * 4 + 2]) + v3 * __ldg(&a[64 + tc * 4 + 3]);
#pragma unroll
    for (int off = 1; off < 16; off <<= 1) {
        p1 += __shfl_xor_sync(0xffffffffu, p1, off);
        p2 += __shfl_xor_sync(0xffffffffu, p2, off);
    }
    if (tc == 0) {
        g_e1[i] = p1;
        g_e2[i] = p2;
        g_E1[i] = __expf(p2);
        g_E2[i] = __expf(ALPHA * p2);
    }
}

// ---------------- kpack: adjacency -> bitmask (ballot) ----------------
__global__ __launch_bounds__(256) void kpack(const int* __restrict__ adj) {
    int i = blockIdx.x;
    int warp = threadIdx.x >> 5, lane = threadIdx.x & 31;
    const int* rowp = adj + (size_t)i * NV;
#pragma unroll
    for (int t = 0; t < 16; t++) {
        int k = warp * 16 + t;
        int v = __ldg(rowp + k * 32 + lane);
        unsigned m = __ballot_sync(0xffffffffu, v > 0);
        if (lane == 0) g_bits[i * 128 + k] = m;
    }
}

// ---------------- kT: transpose + bf16 hi/lo split of Wh -> g_WhC ------------
__global__ __launch_bounds__(256) void kT_split() {
    __shared__ float t[64][65];
    int tid = threadIdx.x;
    int j0 = blockIdx.x * 64;
#pragma unroll
    for (int q = 0; q < 4; q++) {
        int u = tid + q * 256;
        int r = u >> 4, c4 = u & 15;
        float4 vv = *(const float4*)&g_Wh[(size_t)(j0 + r) * 64 + c4 * 4];
        t[r][c4 * 4 + 0] = vv.x; t[r][c4 * 4 + 1] = vv.y;
        t[r][c4 * 4 + 2] = vv.z; t[r][c4 * 4 + 3] = vv.w;
    }
    __syncthreads();
    int c = tid >> 2;
    int jq = (tid & 3) * 16;
    uint2 outv[8];
#pragma unroll
    for (int s = 0; s < 8; s++) {
        float w0 = t[jq + s * 2 + 0][c];
        float w1 = t[jq + s * 2 + 1][c];
        uint32_t hp;
        asm("cvt.rn.bf16x2.f32 %0, %1, %2;" : "=r"(hp) : "f"(w1), "f"(w0));
        float h0 = __uint_as_float(hp << 16);
        float h1 = __uint_as_float(hp & 0xffff0000u);
        float l0 = w0 - h0, l1 = w1 - h1;
        uint32_t lp;
        asm("cvt.rn.bf16x2.f32 %0, %1, %2;" : "=r"(lp) : "f"(l1), "f"(l0));
        outv[s] = make_uint2(hp, lp);
    }
    uint2* dst = &g_WhC[(size_t)c * (NV / 2) + ((j0 + jq) >> 1)];
#pragma unroll
    for (int s = 0; s < 8; s++) dst[s] = outv[s];
}

// ---------------- K2: per-row m, A, B, thE, 1/denominator ----------------
__global__ __launch_bounds__(256) void k2_denom() {
    __shared__ float sE1[NV];
    __shared__ float sE2[NV];
    __shared__ float red[8];
    int tid = threadIdx.x;
#pragma unroll
    for (int t = 0; t < 4; t++) {
        ((float4*)sE1)[tid + t * 256] = ((const float4*)g_E1)[tid + t * 256];
        ((float4*)sE2)[tid + t * 256] = ((const float4*)g_E2)[tid + t * 256];
    }
    float mx = -1e30f;
#pragma unroll
    for (int t = 0; t < 4; t++) {
        float4 v = ((const float4*)g_e2)[tid + t * 256];
        mx = fmaxf(fmaxf(mx, v.x), fmaxf(fmaxf(v.y, v.z), v.w));
    }
#pragma unroll
    for (int o = 16; o > 0; o >>= 1) mx = fmaxf(mx, __shfl_xor_sync(0xffffffffu, mx, o));
    if ((tid & 31) == 0) red[tid >> 5] = mx;
    __syncthreads();
    float e2max = red[0];
#pragma unroll
    for (int w = 1; w < 8; w++) e2max = fmaxf(e2max, red[w]);

    int il = tid >> 4;
    int sub = tid & 15;
    int i = blockIdx.x * 16 + il;
    float e1v = g_e1[i];
    float s = e1v + e2max;
    float m = s > 0.f ? s : ALPHA * s;
    float A = __expf(e1v - m);
    float B = __expf(ALPHA * e1v - m);
    float thE = __expf(-e1v);

    float d = 0.f;
#pragma unroll 4
    for (int t = 0; t < 64; t++) {
        int j = sub * 4 + t * 64;
        float4 E1v = *(const float4*)&sE1[j];
        float4 E2v = *(const float4*)&sE2[j];
        d += (E1v.x > thE) ? A * E1v.x : B * E2v.x;
        d += (E1v.y > thE) ? A * E1v.y : B * E2v.y;
        d += (E1v.z > thE) ? A * E1v.z : B * E2v.z;
        d += (E1v.w > thE) ? A * E1v.w : B * E2v.w;
    }
#pragma unroll
    for (int o = 8; o > 0; o >>= 1) d += __shfl_xor_sync(0xffffffffu, d, o);
    if (sub == 0) {
        g_A[i] = A; g_B[i] = B; g_thE[i] = thE;
        g_dinv[i] = 1.f / d;
    }
}

// ---------------- A-fragment pair build ----------------
__device__ __forceinline__ void build_pair(unsigned ax, unsigned ay,
                                           float e1x, float e1y,
                                           float e2x, float e2y,
                                           float Ai, float Bi, float th,
                                           uint32_t& hi, uint32_t& lo) {
    float w0 = ax ? ((e1x > th) ? Ai * e1x : Bi * e2x) : 0.f;
    float w1 = ay ? ((e1y > th) ? Ai * e1y : Bi * e2y) : 0.f;
    uint32_t h;
    asm("cvt.rn.bf16x2.f32 %0, %1, %2;" : "=r"(h) : "f"(w1), "f"(w0));
    float h0 = __uint_as_float(h << 16);
    float h1 = __uint_as_float(h & 0xffff0000u);
    float l0 = w0 - h0, l1 = w1 - h1;
    uint32_t l;
    asm("cvt.rn.bf16x2.f32 %0, %1, %2;" : "=r"(l) : "f"(l1), "f"(l0));
    hi = h; lo = l;
}

#define MMA_BF16(c0, c1, c2, c3, a0, a1, a2, a3, b0, b1)                        \
    asm("mma.sync.aligned.m16n8k16.row.col.f32.bf16.bf16.f32 "                 \
        "{%0,%1,%2,%3}, {%4,%5,%6,%7}, {%8,%9}, {%0,%1,%2,%3};"                \
        : "+f"(c0), "+f"(c1), "+f"(c2), "+f"(c3)                               \
        : "r"(a0), "r"(a1), "r"(a2), "r"(a3), "r"(b0), "r"(b1))

// ---------------- K3: masked GEMM on tensor cores (bit adjacency) ------------
// Grid 512 = 32 rb (128 i) x 16 jt (256 j). 4 warps/CTA, warp = 32 rows.
// Adjacency from g_bits (1 LDG.32 per row per 32 j). B loads pipelined depth-1.
__global__ __launch_bounds__(128, 4) void k3_main() {
    int tid = threadIdx.x;
    int warp = tid >> 5, lane = tid & 31;
    int gid = lane >> 2, tg = lane & 3;
    int rb = blockIdx.x >> 4;
    int jt = blockIdx.x & 15;
    int jbase = jt << 8;

    int base = rb * 128 + warp * 32;
    int r0 = base + gid, r1 = r0 + 8, r2 = r0 + 16, r3 = r0 + 24;
    float Ai0 = __ldg(&g_A[r0]), Bi0 = __ldg(&g_B[r0]), th0 = __ldg(&g_thE[r0]);
    float Ai1 = __ldg(&g_A[r1]), Bi1 = __ldg(&g_B[r1]), th1 = __ldg(&g_thE[r1]);
    float Ai2 = __ldg(&g_A[r2]), Bi2 = __ldg(&g_B[r2]), th2 = __ldg(&g_thE[r2]);
    float Ai3 = __ldg(&g_A[r3]), Bi3 = __ldg(&g_B[r3]), th3 = __ldg(&g_thE[r3]);

    int wb = jbase >> 5;   // 8 words per row cover this jt segment
    const unsigned* bw0 = g_bits + (size_t)r0 * 128 + wb;
    const unsigned* bw1 = g_bits + (size_t)r1 * 128 + wb;
    const unsigned* bw2 = g_bits + (size_t)r2 * 128 + wb;
    const unsigned* bw3 = g_bits + (size_t)r3 * 128 + wb;

    float acc[2][8][4];
#pragma unroll
    for (int m = 0; m < 2; m++)
#pragma unroll
        for (int n = 0; n < 8; n++)
#pragma unroll
            for (int q = 0; q < 4; q++) acc[m][n][q] = 0.f;

    unsigned nw0 = __ldg(bw0), nw1 = __ldg(bw1), nw2 = __ldg(bw2), nw3 = __ldg(bw3);

    for (int p = 0; p < 8; ++p) {
        unsigned cw0 = nw0, cw1 = nw1, cw2 = nw2, cw3 = nw3;
        if (p < 7) {
            nw0 = __ldg(bw0 + p + 1); nw1 = __ldg(bw1 + p + 1);
            nw2 = __ldg(bw2 + p + 1); nw3 = __ldg(bw3 + p + 1);
        }
#pragma unroll
        for (int h = 0; h < 2; ++h) {
            int kt = p * 2 + h;
            int boff = h * 16 + tg * 2;
            int gj = jbase + kt * 16 + tg * 2;

            float2 e10 = __ldg((const float2*)&g_E1[gj]);
            float2 e18 = __ldg((const float2*)&g_E1[gj + 8]);
            float2 e20 = __ldg((const float2*)&g_E2[gj]);
            float2 e28 = __ldg((const float2*)&g_E2[gj + 8]);

            unsigned m0 = cw0 >> boff, m1 = cw1 >> boff;
            unsigned m2 = cw2 >> boff, m3 = cw3 >> boff;

            uint32_t ah[2][4], al[2][4];
            build_pair(m0 & 1, m0 & 2, e10.x, e10.y, e20.x, e20.y, Ai0, Bi0, th0, ah[0][0], al[0][0]);
            build_pair(m1 & 1, m1 & 2, e10.x, e10.y, e20.x, e20.y, Ai1, Bi1, th1, ah[0][1], al[0][1]);
            build_pair((m0 >> 8) & 1, (m0 >> 8) & 2, e18.x, e18.y, e28.x, e28.y, Ai0, Bi0, th0, ah[0][2], al[0][2]);
            build_pair((m1 >> 8) & 1, (m1 >> 8) & 2, e18.x, e18.y, e28.x, e28.y, Ai1, Bi1, th1, ah[0][3], al[0][3]);
            build_pair(m2 & 1, m2 & 2, e10.x, e10.y, e20.x, e20.y, Ai2, Bi2, th2, ah[1][0], al[1][0]);
            build_pair(m3 & 1, m3 & 2, e10.x, e10.y, e20.x, e20.y, Ai3, Bi3, th3, ah[1][1], al[1][1]);
            build_pair((m2 >> 8) & 1, (m2 >> 8) & 2, e18.x, e18.y, e28.x, e28.y, Ai2, Bi2, th2, ah[1][2], al[1][2]);
            build_pair((m3 >> 8) & 1, (m3 >> 8) & 2, e18.x, e18.y, e28.x, e28.y, Ai3, Bi3, th3, ah[1][3], al[1][3]);

            // B loads pipelined depth-1 across the 8 n-groups
            size_t bj = (size_t)gj >> 1;
            const uint2* bp = &g_WhC[(size_t)gid * (NV / 2) + bj];
            uint2 b0c = __ldg(bp), b1c = __ldg(bp + 4);
#pragma unroll
            for (int n = 0; n < 8; n++) {
                uint2 b0n, b1n;
                if (n < 7) {
                    const uint2* q = bp + (size_t)(n + 1) * 8 * (NV / 2);
                    b0n = __ldg(q); b1n = __ldg(q + 4);
                }
#pragma unroll
                for (int m = 0; m < 2; m++) {
                    MMA_BF16(acc[m][n][0], acc[m][n][1], acc[m][n][2], acc[m][n][3],
                             ah[m][0], ah[m][1], ah[m][2], ah[m][3], b0c.x, b1c.x);
                    MMA_BF16(acc[m][n][0], acc[m][n][1], acc[m][n][2], acc[m][n][3],
                             ah[m][0], ah[m][1], ah[m][2], ah[m][3], b0c.y, b1c.y);
                    MMA_BF16(acc[m][n][0], acc[m][n][1], acc[m][n][2], acc[m][n][3],
                             al[m][0], al[m][1], al[m][2], al[m][3], b0c.x, b1c.x);
                }
                b0c = b0n; b1c = b1n;
            }
        }
    }

    // ---- epilogue ----
    float* dst = g_part[jt];
#pragma unroll
    for (int n = 0; n < 8; n++) {
        int c = n * 8 + tg * 2;
        *(float2*)&dst[(size_t)r0 * 64 + c] = make_float2(acc[0][n][0], acc[0][n][1]);
        *(float2*)&dst[(size_t)r1 * 64 + c] = make_float2(acc[0][n][2], acc[0][n][3]);
        *(float2*)&dst[(size_t)r2 * 64 + c] = make_float2(acc[1][n][0], acc[1][n][1]);
        *(float2*)&dst[(size_t)r3 * 64 + c] = make_float2(acc[1][n][2], acc[1][n][3]);
    }
}

// ---------------- K4: combine 16 partials, scale, ELU ----------------
__global__ __launch_bounds__(256) void k4_out(float* __restrict__ out) {
    int v4 = blockIdx.x * 256 + threadIdx.x;
    float4 s = __ldg(&((const float4*)g_part[0])[v4]);
#pragma unroll
    for (int p = 1; p < 16; p++) {
        float4 t = __ldg(&((const float4*)g_part[p])[v4]);
        s.x += t.x; s.y += t.y; s.z += t.z; s.w += t.w;
    }
    int i = v4 >> 4;
    float di = g_dinv[i];
    s.x *= di; s.y *= di; s.z *= di; s.w *= di;
    s.x = s.x > 0.f ? s.x : (__expf(s.x) - 1.f);
    s.y = s.y > 0.f ? s.y : (__expf(s.y) - 1.f);
    s.z = s.z > 0.f ? s.z : (__expf(s.z) - 1.f);
    s.w = s.w > 0.f ? s.w : (__expf(s.w) - 1.f);
    ((float4*)out)[v4] = s;
}

// ---------------- launch ----------------
extern "C" void kernel_launch(void* const* d_in, const int* in_sizes, int n_in,
                              void* d_out, int out_size) {
    const float* H = (const float*)d_in[0];
    const int* adj = (const int*)d_in[1];
    const float* W = (const float*)d_in[2];
    const float* a = (const float*)d_in[3];
    float* out = (float*)d_out;

    kpack<<<4096, 256>>>(adj);
    k1_wh<<<256, 256>>>(H, W, a);
    kT_split<<<64, 256>>>();
    k2_denom<<<256, 256>>>();
    k3_main<<<512, 128>>>();
    k4_out<<<256, 256>>>(out);
}

// round 11
// speedup vs baseline: 1.0564x; 1.0564x over previous
#include <cuda_runtime.h>
#include <cuda_fp16.h>
#include <cstdint>

#define NV 4096
#define ALPHA 0.2f

// ---------------- device scratch ----------------
__device__ float g_Wh[NV * 64];
__device__ float g_e1[NV], g_e2[NV];
__device__ float g_E1[NV], g_E2[NV];
__device__ float g_A[NV], g_B[NV], g_thE[NV], g_dinv[NV];
__device__ float g_part[4][NV * 64];
__device__ uint2 g_WhC[64 * (NV / 2)];   // [c][j/2] = {f16x2 hi pair, f16x2 lo pair}

// ---------------- K1: Wh = H@W + e1/e2 + E1/E2 ----------------
__global__ __launch_bounds__(256) void k1_wh(const float* __restrict__ H,
                                             const float* __restrict__ W,
                                             const float* __restrict__ a) {
    __shared__ float Hs[16][68];
    __shared__ float Ws[64][64];
    int tid = threadIdx.x;
    int tr = tid >> 4;
    int tc = tid & 15;
    int row0 = blockIdx.x * 16;

    unsigned long long acc[2] = {0ull, 0ull};

    for (int kk = 0; kk < 256; kk += 64) {
#pragma unroll
        for (int t = 0; t < 4; t++) {
            int u = tid + t * 256;
            int r = u >> 4, c4 = u & 15;
            *(float4*)&Ws[r][c4 * 4] = *(const float4*)&W[(size_t)(kk + r) * 64 + c4 * 4];
        }
        *(float4*)&Hs[tr][tc * 4] = *(const float4*)&H[(size_t)(row0 + tr) * 256 + kk + tc * 4];
        __syncthreads();
#pragma unroll 8
        for (int k = 0; k < 64; k++) {
            float4 w4 = *(const float4*)&Ws[k][tc * 4];
            unsigned long long w01, w23, hp;
            asm("mov.b64 %0, {%1, %2};" : "=l"(w01) : "f"(w4.x), "f"(w4.y));
            asm("mov.b64 %0, {%1, %2};" : "=l"(w23) : "f"(w4.z), "f"(w4.w));
            float h = Hs[tr][k];
            asm("mov.b64 %0, {%1, %1};" : "=l"(hp) : "f"(h));
            asm("fma.rn.f32x2 %0, %1, %2, %0;" : "+l"(acc[0]) : "l"(hp), "l"(w01));
            asm("fma.rn.f32x2 %0, %1, %2, %0;" : "+l"(acc[1]) : "l"(hp), "l"(w23));
        }
        __syncthreads();
    }

    float v0 = __uint_as_float((uint32_t)acc[0]);
    float v1 = __uint_as_float((uint32_t)(acc[0] >> 32));
    float v2 = __uint_as_float((uint32_t)acc[1]);
    float v3 = __uint_as_float((uint32_t)(acc[1] >> 32));

    int i = row0 + tr;
    *(float4*)&g_Wh[(size_t)i * 64 + tc * 4] = make_float4(v0, v1, v2, v3);

    float p1 = v0 * __ldg(&a[tc * 4]) + v1 * __ldg(&a[tc * 4 + 1])
             + v2 * __ldg(&a[tc * 4 + 2]) + v3 * __ldg(&a[tc * 4 + 3]);
    float p2 = v0 * __ldg(&a[64 + tc * 4]) + v1 * __ldg(&a[64 + tc * 4 + 1])
             + v2 * __ldg(&a[64 + tc * 4 + 2]) + v3 * __ldg(&a[64 + tc * 4 + 3]);
#pragma unroll
    for (int off = 1; off < 16; off <<= 1) {
        p1 += __shfl_xor_sync(0xffffffffu, p1, off);
        p2 += __shfl_xor_sync(0xffffffffu, p2, off);
    }
    if (tc == 0) {
        g_e1[i] = p1;
        g_e2[i] = p2;
        g_E1[i] = __expf(p2);
        g_E2[i] = __expf(ALPHA * p2);
    }
}

// ---------------- kT: transpose + fp16 hi/lo split of Wh -> g_WhC ------------
__global__ __launch_bounds__(256) void kT_split() {
    __shared__ float t[64][65];
    int tid = threadIdx.x;
    int j0 = blockIdx.x * 64;
#pragma unroll
    for (int q = 0; q < 4; q++) {
        int u = tid + q * 256;
        int r = u >> 4, c4 = u & 15;
        float4 vv = *(const float4*)&g_Wh[(size_t)(j0 + r) * 64 + c4 * 4];
        t[r][c4 * 4 + 0] = vv.x; t[r][c4 * 4 + 1] = vv.y;
        t[r][c4 * 4 + 2] = vv.z; t[r][c4 * 4 + 3] = vv.w;
    }
    __syncthreads();
    int c = tid >> 2;
    int jq = (tid & 3) * 16;
    uint2 outv[8];
#pragma unroll
    for (int s = 0; s < 8; s++) {
        float w0 = t[jq + s * 2 + 0][c];
        float w1 = t[jq + s * 2 + 1][c];
        __half2 h = __floats2half2_rn(w0, w1);
        float2 back = __half22float2(h);
        __half2 l = __floats2half2_rn(w0 - back.x, w1 - back.y);
        outv[s] = make_uint2(*(uint32_t*)&h, *(uint32_t*)&l);
    }
    uint2* dst = &g_WhC[(size_t)c * (NV / 2) + ((j0 + jq) >> 1)];
#pragma unroll
    for (int s = 0; s < 8; s++) dst[s] = outv[s];
}

// ---------------- K2: per-row denominator (512 blocks x 8 rows, warp/row) ----
__global__ __launch_bounds__(256) void k2_denom() {
    __shared__ float sE1[NV];
    __shared__ float sE2[NV];
    __shared__ float red[8];
    int tid = threadIdx.x;
    int warp = tid >> 5, lane = tid & 31;
#pragma unroll
    for (int t = 0; t < 4; t++) {
        ((float4*)sE1)[tid + t * 256] = __ldg(&((const float4*)g_E1)[tid + t * 256]);
        ((float4*)sE2)[tid + t * 256] = __ldg(&((const float4*)g_E2)[tid + t * 256]);
    }
    float mx = -1e30f;
#pragma unroll
    for (int t = 0; t < 4; t++) {
        float4 v = __ldg(&((const float4*)g_e2)[tid + t * 256]);
        mx = fmaxf(fmaxf(mx, v.x), fmaxf(fmaxf(v.y, v.z), v.w));
    }
#pragma unroll
    for (int o = 16; o > 0; o >>= 1) mx = fmaxf(mx, __shfl_xor_sync(0xffffffffu, mx, o));
    if (lane == 0) red[warp] = mx;
    __syncthreads();
    float e2max = red[0];
#pragma unroll
    for (int w = 1; w < 8; w++) e2max = fmaxf(e2max, red[w]);

    int i = blockIdx.x * 8 + warp;
    float e1v = g_e1[i];
    float s = e1v + e2max;
    float m = s > 0.f ? s : ALPHA * s;
    float A = __expf(e1v - m);
    float B = __expf(ALPHA * e1v - m);
    float thE = __expf(-e1v);

    float d = 0.f;
#pragma unroll 8
    for (int t = 0; t < 32; t++) {
        int j = (lane + t * 32) * 4;
        float4 E1v = *(const float4*)&sE1[j];
        float4 E2v = *(const float4*)&sE2[j];
        d += (E1v.x > thE) ? A * E1v.x : B * E2v.x;
        d += (E1v.y > thE) ? A * E1v.y : B * E2v.y;
        d += (E1v.z > thE) ? A * E1v.z : B * E2v.z;
        d += (E1v.w > thE) ? A * E1v.w : B * E2v.w;
    }
#pragma unroll
    for (int o = 16; o > 0; o >>= 1) d += __shfl_xor_sync(0xffffffffu, d, o);
    if (lane == 0) {
        g_A[i] = A; g_B[i] = B; g_thE[i] = thE;
        g_dinv[i] = 1.f / d;
    }
}

// ---------------- A-fragment build: masked weight -> single fp16 pair --------
__device__ __forceinline__ uint32_t build_a(int ax, int ay,
                                            float e1x, float e1y,
                                            float e2x, float e2y,
                                            float Ai, float Bi, float th) {
    float w0 = (ax > 0) ? ((e1x > th) ? Ai * e1x : Bi * e2x) : 0.f;
    float w1 = (ay > 0) ? ((e1y > th) ? Ai * e1y : Bi * e2y) : 0.f;
    __half2 h = __floats2half2_rn(w0, w1);
    return *(uint32_t*)&h;
}

#define MMA_F16(c0, c1, c2, c3, a0, a1, a2, a3, b0, b1)                         \
    asm("mma.sync.aligned.m16n8k16.row.col.f32.f16.f16.f32 "                   \
        "{%0,%1,%2,%3}, {%4,%5,%6,%7}, {%8,%9}, {%0,%1,%2,%3};"                \
        : "+f"(c0), "+f"(c1), "+f"(c2), "+f"(c3)                               \
        : "r"(a0), "r"(a1), "r"(a2), "r"(a3), "r"(b0), "r"(b1))

// ---------------- K3: masked GEMM, fp16 A + fp16 hi/lo B, 2 MMAs -------------
// Grid 512 = 128 rb (32 i) x 4 jseg (1024 j). 4 warps/CTA, each warp a
// DISTINCT 256-j quarter; cross-warp smem reduction -> only 4 partial planes.
__global__ __launch_bounds__(128, 3) void k3_main(const int* __restrict__ adj) {
    __shared__ float sred[4 * 32 * 68];   // [warp][row][col], pad 68
    int tid = threadIdx.x;
    int warp = tid >> 5, lane = tid & 31;
    int gid = lane >> 2, tg = lane & 3;
    int rb = blockIdx.x >> 2;
    int jseg = blockIdx.x & 3;
    int jq = jseg * 1024 + warp * 256;

    int base = rb * 32;
    int r0 = base + gid, r1 = r0 + 8, r2 = r0 + 16, r3 = r0 + 24;
    float Ai0 = __ldg(&g_A[r0]), Bi0 = __ldg(&g_B[r0]), th0 = __ldg(&g_thE[r0]);
    float Ai1 = __ldg(&g_A[r1]), Bi1 = __ldg(&g_B[r1]), th1 = __ldg(&g_thE[r1]);
    float Ai2 = __ldg(&g_A[r2]), Bi2 = __ldg(&g_B[r2]), th2 = __ldg(&g_thE[r2]);
    float Ai3 = __ldg(&g_A[r3]), Bi3 = __ldg(&g_B[r3]), th3 = __ldg(&g_thE[r3]);
    const int* a0p = adj + (size_t)r0 * NV + jq;
    const int* a1p = adj + (size_t)r1 * NV + jq;
    const int* a2p = adj + (size_t)r2 * NV + jq;
    const int* a3p = adj + (size_t)r3 * NV + jq;

    float acc[2][8][4];
#pragma unroll
    for (int m = 0; m < 2; m++)
#pragma unroll
        for (int n = 0; n < 8; n++)
#pragma unroll
            for (int q = 0; q < 4; q++) acc[m][n][q] = 0.f;

    int jc = tg * 2;
    int2 p0a = __ldg((const int2*)(a0p + jc)), p0b = __ldg((const int2*)(a0p + jc + 8));
    int2 p1a = __ldg((const int2*)(a1p + jc)), p1b = __ldg((const int2*)(a1p + jc + 8));
    int2 p2a = __ldg((const int2*)(a2p + jc)), p2b = __ldg((const int2*)(a2p + jc + 8));
    int2 p3a = __ldg((const int2*)(a3p + jc)), p3b = __ldg((const int2*)(a3p + jc + 8));

    for (int kt = 0; kt < 16; ++kt) {
        int j0 = kt * 16 + tg * 2;
        int gj = jq + j0;

        float2 e10 = __ldg((const float2*)&g_E1[gj]);
        float2 e18 = __ldg((const float2*)&g_E1[gj + 8]);
        float2 e20 = __ldg((const float2*)&g_E2[gj]);
        float2 e28 = __ldg((const float2*)&g_E2[gj + 8]);

        int2 c0a = p0a, c0b = p0b, c1a = p1a, c1b = p1b;
        int2 c2a = p2a, c2b = p2b, c3a = p3a, c3b = p3b;
        if (kt < 15) {
            int jn = j0 + 16;
            p0a = __ldg((const int2*)(a0p + jn)); p0b = __ldg((const int2*)(a0p + jn + 8));
            p1a = __ldg((const int2*)(a1p + jn)); p1b = __ldg((const int2*)(a1p + jn + 8));
            p2a = __ldg((const int2*)(a2p + jn)); p2b = __ldg((const int2*)(a2p + jn + 8));
            p3a = __ldg((const int2*)(a3p + jn)); p3b = __ldg((const int2*)(a3p + jn + 8));
        }

        uint32_t ah[2][4];
        ah[0][0] = build_a(c0a.x, c0a.y, e10.x, e10.y, e20.x, e20.y, Ai0, Bi0, th0);
        ah[0][1] = build_a(c1a.x, c1a.y, e10.x, e10.y, e20.x, e20.y, Ai1, Bi1, th1);
        ah[0][2] = build_a(c0b.x, c0b.y, e18.x, e18.y, e28.x, e28.y, Ai0, Bi0, th0);
        ah[0][3] = build_a(c1b.x, c1b.y, e18.x, e18.y, e28.x, e28.y, Ai1, Bi1, th1);
        ah[1][0] = build_a(c2a.x, c2a.y, e10.x, e10.y, e20.x, e20.y, Ai2, Bi2, th2);
        ah[1][1] = build_a(c3a.x, c3a.y, e10.x, e10.y, e20.x, e20.y, Ai3, Bi3, th3);
        ah[1][2] = build_a(c2b.x, c2b.y, e18.x, e18.y, e28.x, e28.y, Ai2, Bi2, th2);
        ah[1][3] = build_a(c3b.x, c3b.y, e18.x, e18.y, e28.x, e28.y, Ai3, Bi3, th3);

        // B loads pipelined depth-1 across the 8 n-groups
        size_t bj = (size_t)gj >> 1;
        const uint2* bp = &g_WhC[(size_t)gid * (NV / 2) + bj];
        uint2 b0c = __ldg(bp), b1c = __ldg(bp + 4);
#pragma unroll
        for (int n = 0; n < 8; n++) {
            uint2 b0n, b1n;
            if (n < 7) {
                const uint2* q = bp + (size_t)(n + 1) * 8 * (NV / 2);
                b0n = __ldg(q); b1n = __ldg(q + 4);
            }
#pragma unroll
            for (int m = 0; m < 2; m++) {
                MMA_F16(acc[m][n][0], acc[m][n][1], acc[m][n][2], acc[m][n][3],
                        ah[m][0], ah[m][1], ah[m][2], ah[m][3], b0c.x, b1c.x);
                MMA_F16(acc[m][n][0], acc[m][n][1], acc[m][n][2], acc[m][n][3],
                        ah[m][0], ah[m][1], ah[m][2], ah[m][3], b0c.y, b1c.y);
            }
            b0c = b0n; b1c = b1n;
        }
    }

    // ---- cross-warp reduction in smem ----
    float* sw = sred + warp * (32 * 68);
#pragma unroll
    for (int n = 0; n < 8; n++) {
        int c = n * 8 + tg * 2;
        *(float2*)&sw[gid * 68 + c]        = make_float2(acc[0][n][0], acc[0][n][1]);
        *(float2*)&sw[(gid + 8) * 68 + c]  = make_float2(acc[0][n][2], acc[0][n][3]);
        *(float2*)&sw[(gid + 16) * 68 + c] = make_float2(acc[1][n][0], acc[1][n][1]);
        *(float2*)&sw[(gid + 24) * 68 + c] = make_float2(acc[1][n][2], acc[1][n][3]);
    }
    __syncthreads();

    float* dst = g_part[jseg];
#pragma unroll
    for (int q = 0; q < 4; q++) {
        int v = tid + q * 128;          // 0..511 float4 slots
        int row = v >> 4;
        int col = (v & 15) * 4;
        int so = row * 68 + col;
        float4 s0 = *(const float4*)&sred[so];
        float4 s1 = *(const float4*)&sred[so + 32 * 68];
        float4 s2 = *(const float4*)&sred[so + 64 * 68];
        float4 s3 = *(const float4*)&sred[so + 96 * 68];
        float4 r;
        r.x = s0.x + s1.x + s2.x + s3.x;
        r.y = s0.y + s1.y + s2.y + s3.y;
        r.z = s0.z + s1.z + s2.z + s3.z;
        r.w = s0.w + s1.w + s2.w + s3.w;
        *(float4*)&dst[(size_t)(base + row) * 64 + col] = r;
    }
}

// ---------------- K4: combine 4 partials, scale, ELU ----------------
__global__ __launch_bounds__(256) void k4_out(float* __restrict__ out) {
    int v4 = blockIdx.x * 256 + threadIdx.x;
    float4 s = __ldg(&((const float4*)g_part[0])[v4]);
#pragma unroll
    for (int p = 1; p < 4; p++) {
        float4 t = __ldg(&((const float4*)g_part[p])[v4]);
        s.x += t.x; s.y += t.y; s.z += t.z; s.w += t.w;
    }
    int i = v4 >> 4;
    float di = g_dinv[i];
    s.x *= di; s.y *= di; s.z *= di; s.w *= di;
    s.x = s.x > 0.f ? s.x : (__expf(s.x) - 1.f);
    s.y = s.y > 0.f ? s.y : (__expf(s.y) - 1.f);
    s.z = s.z > 0.f ? s.z : (__expf(s.z) - 1.f);
    s.w = s.w > 0.f ? s.w : (__expf(s.w) - 1.f);
    ((float4*)out)[v4] = s;
}

// ---------------- launch ----------------
extern "C" void kernel_launch(void* const* d_in, const int* in_sizes, int n_in,
                              void* d_out, int out_size) {
    const float* H = (const float*)d_in[0];
    const int* adj = (const int*)d_in[1];
    const float* W = (const float*)d_in[2];
    const float* a = (const float*)d_in[3];
    float* out = (float*)d_out;

    k1_wh<<<256, 256>>>(H, W, a);
    kT_split<<<64, 256>>>();
    k2_denom<<<512, 256>>>();
    k3_main<<<512, 128>>>(adj);
    k4_out<<<256, 256>>>(out);
}

// round 12
// speedup vs baseline: 1.2931x; 1.2241x over previous
#include <cuda_runtime.h>
#include <cuda_fp16.h>
#include <cstdint>

#define NV 4096
#define ALPHA 0.2f

// ---------------- device scratch ----------------
__device__ float g_Wh[NV * 64];
__device__ float g_e1[NV], g_e2[NV];
__device__ float g_E1[NV], g_E2[NV];
__device__ float g_A[NV], g_B[NV], g_thE[NV], g_dinv[NV];
__device__ float g_part[4][NV * 64];
__device__ uint2 g_WhC[64 * (NV / 2)];   // [c][j/2] = {f16x2 hi pair, f16x2 lo pair}

// ---------------- K1: Wh = H@W + e1/e2 + E1/E2 ----------------
__global__ __launch_bounds__(256) void k1_wh(const float* __restrict__ H,
                                             const float* __restrict__ W,
                                             const float* __restrict__ a) {
    __shared__ float Hs[16][68];
    __shared__ float Ws[64][64];
    int tid = threadIdx.x;
    int tr = tid >> 4;
    int tc = tid & 15;
    int row0 = blockIdx.x * 16;

    unsigned long long acc[2] = {0ull, 0ull};

    for (int kk = 0; kk < 256; kk += 64) {
#pragma unroll
        for (int t = 0; t < 4; t++) {
            int u = tid + t * 256;
            int r = u >> 4, c4 = u & 15;
            *(float4*)&Ws[r][c4 * 4] = *(const float4*)&W[(size_t)(kk + r) * 64 + c4 * 4];
        }
        *(float4*)&Hs[tr][tc * 4] = *(const float4*)&H[(size_t)(row0 + tr) * 256 + kk + tc * 4];
        __syncthreads();
#pragma unroll 8
        for (int k = 0; k < 64; k++) {
            float4 w4 = *(const float4*)&Ws[k][tc * 4];
            unsigned long long w01, w23, hp;
            asm("mov.b64 %0, {%1, %2};" : "=l"(w01) : "f"(w4.x), "f"(w4.y));
            asm("mov.b64 %0, {%1, %2};" : "=l"(w23) : "f"(w4.z), "f"(w4.w));
            float h = Hs[tr][k];
            asm("mov.b64 %0, {%1, %1};" : "=l"(hp) : "f"(h));
            asm("fma.rn.f32x2 %0, %1, %2, %0;" : "+l"(acc[0]) : "l"(hp), "l"(w01));
            asm("fma.rn.f32x2 %0, %1, %2, %0;" : "+l"(acc[1]) : "l"(hp), "l"(w23));
        }
        __syncthreads();
    }

    float v0 = __uint_as_float((uint32_t)acc[0]);
    float v1 = __uint_as_float((uint32_t)(acc[0] >> 32));
    float v2 = __uint_as_float((uint32_t)acc[1]);
    float v3 = __uint_as_float((uint32_t)(acc[1] >> 32));

    int i = row0 + tr;
    *(float4*)&g_Wh[(size_t)i * 64 + tc * 4] = make_float4(v0, v1, v2, v3);

    float p1 = v0 * __ldg(&a[tc * 4]) + v1 * __ldg(&a[tc * 4 + 1])
             + v2 * __ldg(&a[tc * 4 + 2]) + v3 * __ldg(&a[tc * 4 + 3]);
    float p2 = v0 * __ldg(&a[64 + tc * 4]) + v1 * __ldg(&a[64 + tc * 4 + 1])
             + v2 * __ldg(&a[64 + tc * 4 + 2]) + v3 * __ldg(&a[64 + tc * 4 + 3]);
#pragma unroll
    for (int off = 1; off < 16; off <<= 1) {
        p1 += __shfl_xor_sync(0xffffffffu, p1, off);
        p2 += __shfl_xor_sync(0xffffffffu, p2, off);
    }
    if (tc == 0) {
        g_e1[i] = p1;
        g_e2[i] = p2;
        g_E1[i] = __expf(p2);
        g_E2[i] = __expf(ALPHA * p2);
    }
}

// ---------------- kT: transpose + fp16 hi/lo split of Wh -> g_WhC ------------
__global__ __launch_bounds__(256) void kT_split() {
    __shared__ float t[64][65];
    int tid = threadIdx.x;
    int j0 = blockIdx.x * 64;
#pragma unroll
    for (int q = 0; q < 4; q++) {
        int u = tid + q * 256;
        int r = u >> 4, c4 = u & 15;
        float4 vv = *(const float4*)&g_Wh[(size_t)(j0 + r) * 64 + c4 * 4];
        t[r][c4 * 4 + 0] = vv.x; t[r][c4 * 4 + 1] = vv.y;
        t[r][c4 * 4 + 2] = vv.z; t[r][c4 * 4 + 3] = vv.w;
    }
    __syncthreads();
    int c = tid >> 2;
    int jq = (tid & 3) * 16;
    uint2 outv[8];
#pragma unroll
    for (int s = 0; s < 8; s++) {
        float w0 = t[jq + s * 2 + 0][c];
        float w1 = t[jq + s * 2 + 1][c];
        __half2 h = __floats2half2_rn(w0, w1);
        float2 back = __half22float2(h);
        __half2 l = __floats2half2_rn(w0 - back.x, w1 - back.y);
        outv[s] = make_uint2(*(uint32_t*)&h, *(uint32_t*)&l);
    }
    uint2* dst = &g_WhC[(size_t)c * (NV / 2) + ((j0 + jq) >> 1)];
#pragma unroll
    for (int s = 0; s < 8; s++) dst[s] = outv[s];
}

// ---------------- K2: per-row denominator ----------------
__global__ __launch_bounds__(256) void k2_denom() {
    __shared__ float sE1[NV];
    __shared__ float sE2[NV];
    __shared__ float red[8];
    int tid = threadIdx.x;
    int warp = tid >> 5, lane = tid & 31;
#pragma unroll
    for (int t = 0; t < 4; t++) {
        ((float4*)sE1)[tid + t * 256] = __ldg(&((const float4*)g_E1)[tid + t * 256]);
        ((float4*)sE2)[tid + t * 256] = __ldg(&((const float4*)g_E2)[tid + t * 256]);
    }
    float mx = -1e30f;
#pragma unroll
    for (int t = 0; t < 4; t++) {
        float4 v = __ldg(&((const float4*)g_e2)[tid + t * 256]);
        mx = fmaxf(fmaxf(mx, v.x), fmaxf(fmaxf(v.y, v.z), v.w));
    }
#pragma unroll
    for (int o = 16; o > 0; o >>= 1) mx = fmaxf(mx, __shfl_xor_sync(0xffffffffu, mx, o));
    if (lane == 0) red[warp] = mx;
    __syncthreads();
    float e2max = red[0];
#pragma unroll
    for (int w = 1; w < 8; w++) e2max = fmaxf(e2max, red[w]);

    int i = blockIdx.x * 8 + warp;
    float e1v = g_e1[i];
    float s = e1v + e2max;
    float m = s > 0.f ? s : ALPHA * s;
    float A = __expf(e1v - m);
    float B = __expf(ALPHA * e1v - m);
    float thE = __expf(-e1v);

    float d = 0.f;
#pragma unroll 8
    for (int t = 0; t < 32; t++) {
        int j = (lane + t * 32) * 4;
        float4 E1v = *(const float4*)&sE1[j];
        float4 E2v = *(const float4*)&sE2[j];
        d += (E1v.x > thE) ? A * E1v.x : B * E2v.x;
        d += (E1v.y > thE) ? A * E1v.y : B * E2v.y;
        d += (E1v.z > thE) ? A * E1v.z : B * E2v.z;
        d += (E1v.w > thE) ? A * E1v.w : B * E2v.w;
    }
#pragma unroll
    for (int o = 16; o > 0; o >>= 1) d += __shfl_xor_sync(0xffffffffu, d, o);
    if (lane == 0) {
        g_A[i] = A; g_B[i] = B; g_thE[i] = thE;
        g_dinv[i] = 1.f / d;
    }
}

// ---------------- A-fragment build ----------------
__device__ __forceinline__ uint32_t build_a(int ax, int ay,
                                            float e1x, float e1y,
                                            float e2x, float e2y,
                                            float Ai, float Bi, float th) {
    float w0 = (ax > 0) ? ((e1x > th) ? Ai * e1x : Bi * e2x) : 0.f;
    float w1 = (ay > 0) ? ((e1y > th) ? Ai * e1y : Bi * e2y) : 0.f;
    __half2 h = __floats2half2_rn(w0, w1);
    return *(uint32_t*)&h;
}

#define MMA_F16(c0, c1, c2, c3, a0, a1, a2, a3, b0, b1)                         \
    asm("mma.sync.aligned.m16n8k16.row.col.f32.f16.f16.f32 "                   \
        "{%0,%1,%2,%3}, {%4,%5,%6,%7}, {%8,%9}, {%0,%1,%2,%3};"                \
        : "+f"(c0), "+f"(c1), "+f"(c2), "+f"(c3)                               \
        : "r"(a0), "r"(a1), "r"(a2), "r"(a3), "r"(b0), "r"(b1))

#define CP_WAIT(n) asm volatile("cp.async.wait_group %0;" :: "n"(n) : "memory")

// ---------------- K3: masked GEMM, per-warp cp.async adj pipeline ------------
// Grid 512 = 128 rb (32 i) x 4 jseg (1024 j). 4 warps/CTA, distinct 256-j
// quarters. adj staged depth-3 via cp.async (warp-private slots, no block
// syncs). 4 CTAs/SM -> single wave.
__global__ __launch_bounds__(128, 4) void k3_main(const int* __restrict__ adj) {
    __shared__ union {
        struct {
            int adjt[4][3][640];    // [warp][stage][row*20 + jj], stride 20 ints
            float E1[4][256];
            float E2[4][256];
        } a;
        float red[4][32][68];
    } su;

    int tid = threadIdx.x;
    int warp = tid >> 5, lane = tid & 31;
    int gid = lane >> 2, tg = lane & 3;
    int rb = blockIdx.x >> 2;
    int jseg = blockIdx.x & 3;
    int jq = jseg * 1024 + warp * 256;
    int base = rb * 32;

    const int* adjw = adj + (size_t)base * NV + jq;   // rows base.., this warp's j-quarter
    int cp_row = lane >> 2;        // reused mapping for cp: u = lane+32q -> row u>>2
    int cp_part = lane & 3;

    // ---- prologue: issue adj tiles 0..2 ----
#pragma unroll
    for (int kt = 0; kt < 3; kt++) {
#pragma unroll
        for (int q = 0; q < 4; q++) {
            int row = cp_row + q * 8;
            unsigned daddr = (unsigned)__cvta_generic_to_shared(
                &su.a.adjt[warp][kt][row * 20 + cp_part * 4]);
            const int* src = adjw + (size_t)row * NV + kt * 16 + cp_part * 4;
            asm volatile("cp.async.cg.shared.global [%0], [%1], 16;"
                         :: "r"(daddr), "l"(src) : "memory");
        }
        asm volatile("cp.async.commit_group;" ::: "memory");
    }

    // ---- stage E for this warp's quarter ----
#pragma unroll
    for (int t = 0; t < 2; t++) {
        int idx = lane + t * 32;       // 64 float4 slots
        float4 v1 = __ldg(&((const float4*)(g_E1 + jq))[idx]);
        *(float4*)&su.a.E1[warp][idx * 4] = v1;
        float4 v2 = __ldg(&((const float4*)(g_E2 + jq))[idx]);
        *(float4*)&su.a.E2[warp][idx * 4] = v2;
    }
    __syncwarp();

    int r0 = base + gid, r1 = r0 + 8, r2 = r0 + 16, r3 = r0 + 24;
    float Ai0 = __ldg(&g_A[r0]), Bi0 = __ldg(&g_B[r0]), th0 = __ldg(&g_thE[r0]);
    float Ai1 = __ldg(&g_A[r1]), Bi1 = __ldg(&g_B[r1]), th1 = __ldg(&g_thE[r1]);
    float Ai2 = __ldg(&g_A[r2]), Bi2 = __ldg(&g_B[r2]), th2 = __ldg(&g_thE[r2]);
    float Ai3 = __ldg(&g_A[r3]), Bi3 = __ldg(&g_B[r3]), th3 = __ldg(&g_thE[r3]);

    float acc[2][8][4];
#pragma unroll
    for (int m = 0; m < 2; m++)
#pragma unroll
        for (int n = 0; n < 8; n++)
#pragma unroll
            for (int q = 0; q < 4; q++) acc[m][n][q] = 0.f;

#pragma unroll
    for (int kt = 0; kt < 16; ++kt) {
        // wait for adj tile kt (see group accounting in commit pattern)
        if (kt <= 13) { CP_WAIT(2); } else if (kt == 14) { CP_WAIT(1); } else { CP_WAIT(0); }
        __syncwarp();

        const int* sa = su.a.adjt[warp][kt % 3];
        int2 c0a = *(const int2*)&sa[gid * 20 + tg * 2];
        int2 c0b = *(const int2*)&sa[gid * 20 + tg * 2 + 8];
        int2 c1a = *(const int2*)&sa[(gid + 8) * 20 + tg * 2];
        int2 c1b = *(const int2*)&sa[(gid + 8) * 20 + tg * 2 + 8];
        int2 c2a = *(const int2*)&sa[(gid + 16) * 20 + tg * 2];
        int2 c2b = *(const int2*)&sa[(gid + 16) * 20 + tg * 2 + 8];
        int2 c3a = *(const int2*)&sa[(gid + 24) * 20 + tg * 2];
        int2 c3b = *(const int2*)&sa[(gid + 24) * 20 + tg * 2 + 8];

        int j0 = kt * 16 + tg * 2;
        float2 e10 = *(const float2*)&su.a.E1[warp][(j0 & 255)];
        float2 e18 = *(const float2*)&su.a.E1[warp][((j0 + 8) & 255)];
        float2 e20 = *(const float2*)&su.a.E2[warp][(j0 & 255)];
        float2 e28 = *(const float2*)&su.a.E2[warp][((j0 + 8) & 255)];

        uint32_t ah[2][4];
        ah[0][0] = build_a(c0a.x, c0a.y, e10.x, e10.y, e20.x, e20.y, Ai0, Bi0, th0);
        ah[0][1] = build_a(c1a.x, c1a.y, e10.x, e10.y, e20.x, e20.y, Ai1, Bi1, th1);
        ah[0][2] = build_a(c0b.x, c0b.y, e18.x, e18.y, e28.x, e28.y, Ai0, Bi0, th0);
        ah[0][3] = build_a(c1b.x, c1b.y, e18.x, e18.y, e28.x, e28.y, Ai1, Bi1, th1);
        ah[1][0] = build_a(c2a.x, c2a.y, e10.x, e10.y, e20.x, e20.y, Ai2, Bi2, th2);
        ah[1][1] = build_a(c3a.x, c3a.y, e10.x, e10.y, e20.x, e20.y, Ai3, Bi3, th3);
        ah[1][2] = build_a(c2b.x, c2b.y, e18.x, e18.y, e28.x, e28.y, Ai2, Bi2, th2);
        ah[1][3] = build_a(c3b.x, c3b.y, e18.x, e18.y, e28.x, e28.y, Ai3, Bi3, th3);

        // issue adj tile kt+3 into slot (kt+3)%3 == kt%3 (just consumed)
        if (kt < 13) {
            int ktn = kt + 3;
#pragma unroll
            for (int q = 0; q < 4; q++) {
                int row = cp_row + q * 8;
                unsigned daddr = (unsigned)__cvta_generic_to_shared(
                    &su.a.adjt[warp][kt % 3][row * 20 + cp_part * 4]);
                const int* src = adjw + (size_t)row * NV + ktn * 16 + cp_part * 4;
                asm volatile("cp.async.cg.shared.global [%0], [%1], 16;"
                             :: "r"(daddr), "l"(src) : "memory");
            }
            asm volatile("cp.async.commit_group;" ::: "memory");
        }

        // B loads pipelined depth-1 across 8 n-groups
        int gj = jq + j0;
        size_t bj = (size_t)gj >> 1;
        const uint2* bp = &g_WhC[(size_t)gid * (NV / 2) + bj];
        uint2 b0c = __ldg(bp), b1c = __ldg(bp + 4);
#pragma unroll
        for (int n = 0; n < 8; n++) {
            uint2 b0n, b1n;
            if (n < 7) {
                const uint2* q = bp + (size_t)(n + 1) * 8 * (NV / 2);
                b0n = __ldg(q); b1n = __ldg(q + 4);
            }
#pragma unroll
            for (int m = 0; m < 2; m++) {
                MMA_F16(acc[m][n][0], acc[m][n][1], acc[m][n][2], acc[m][n][3],
                        ah[m][0], ah[m][1], ah[m][2], ah[m][3], b0c.x, b1c.x);
                MMA_F16(acc[m][n][0], acc[m][n][1], acc[m][n][2], acc[m][n][3],
                        ah[m][0], ah[m][1], ah[m][2], ah[m][3], b0c.y, b1c.y);
            }
            b0c = b0n; b1c = b1n;
        }
    }

    // ---- cross-warp reduction (smem union reuse) ----
    __syncthreads();
    float* sw = &su.red[warp][0][0];
#pragma unroll
    for (int n = 0; n < 8; n++) {
        int c = n * 8 + tg * 2;
        *(float2*)&sw[gid * 68 + c]        = make_float2(acc[0][n][0], acc[0][n][1]);
        *(float2*)&sw[(gid + 8) * 68 + c]  = make_float2(acc[0][n][2], acc[0][n][3]);
        *(float2*)&sw[(gid + 16) * 68 + c] = make_float2(acc[1][n][0], acc[1][n][1]);
        *(float2*)&sw[(gid + 24) * 68 + c] = make_float2(acc[1][n][2], acc[1][n][3]);
    }
    __syncthreads();

    float* dst = g_part[jseg];
#pragma unroll
    for (int q = 0; q < 4; q++) {
        int v = tid + q * 128;
        int row = v >> 4;
        int col = (v & 15) * 4;
        float4 s0 = *(const float4*)&su.red[0][row][col];
        float4 s1 = *(const float4*)&su.red[1][row][col];
        float4 s2 = *(const float4*)&su.red[2][row][col];
        float4 s3 = *(const float4*)&su.red[3][row][col];
        float4 r;
        r.x = s0.x + s1.x + s2.x + s3.x;
        r.y = s0.y + s1.y + s2.y + s3.y;
        r.z = s0.z + s1.z + s2.z + s3.z;
        r.w = s0.w + s1.w + s2.w + s3.w;
        *(float4*)&dst[(size_t)(base + row) * 64 + col] = r;
    }
}

// ---------------- K4: combine 4 partials, scale, ELU ----------------
__global__ __launch_bounds__(256) void k4_out(float* __restrict__ out) {
    int v4 = blockIdx.x * 256 + threadIdx.x;
    float4 s = __ldg(&((const float4*)g_part[0])[v4]);
#pragma unroll
    for (int p = 1; p < 4; p++) {
        float4 t = __ldg(&((const float4*)g_part[p])[v4]);
        s.x += t.x; s.y += t.y; s.z += t.z; s.w += t.w;
    }
    int i = v4 >> 4;
    float di = g_dinv[i];
    s.x *= di; s.y *= di; s.z *= di; s.w *= di;
    s.x = s.x > 0.f ? s.x : (__expf(s.x) - 1.f);
    s.y = s.y > 0.f ? s.y : (__expf(s.y) - 1.f);
    s.z = s.z > 0.f ? s.z : (__expf(s.z) - 1.f);
    s.w = s.w > 0.f ? s.w : (__expf(s.w) - 1.f);
    ((float4*)out)[v4] = s;
}

// ---------------- launch ----------------
extern "C" void kernel_launch(void* const* d_in, const int* in_sizes, int n_in,
                              void* d_out, int out_size) {
    const float* H = (const float*)d_in[0];
    const int* adj = (const int*)d_in[1];
    const float* W = (const float*)d_in[2];
    const float* a = (const float*)d_in[3];
    float* out = (float*)d_out;

    k1_wh<<<256, 256>>>(H, W, a);
    kT_split<<<64, 256>>>();
    k2_denom<<<512, 256>>>();
    k3_main<<<512, 128>>>(adj);
    k4_out<<<256, 256>>>(out);
}

// round 13
// speedup vs baseline: 1.3978x; 1.0809x over previous
#include <cuda_runtime.h>
#include <cuda_fp16.h>
#include <cstdint>

#define NV 4096
#define ALPHA 0.2f

// ---------------- device scratch ----------------
__device__ float g_Wh[NV * 64];
__device__ float g_e1[NV], g_e2[NV];
__device__ float g_E1[NV], g_E2[NV];
__device__ float g_A[NV], g_B[NV], g_thE[NV], g_dinv[NV];
__device__ float g_part[4][NV * 64];
__device__ uint32_t g_WhH[64 * (NV / 2)];   // [c][j/2] = f16x2 pair

// ---------------- K1: Wh = H@W + e1/e2 + E1/E2 ----------------
__global__ __launch_bounds__(256) void k1_wh(const float* __restrict__ H,
                                             const float* __restrict__ W,
                                             const float* __restrict__ a) {
    __shared__ float Hs[16][68];
    __shared__ float Ws[64][64];
    int tid = threadIdx.x;
    int tr = tid >> 4;
    int tc = tid & 15;
    int row0 = blockIdx.x * 16;

    unsigned long long acc[2] = {0ull, 0ull};

    for (int kk = 0; kk < 256; kk += 64) {
#pragma unroll
        for (int t = 0; t < 4; t++) {
            int u = tid + t * 256;
            int r = u >> 4, c4 = u & 15;
            *(float4*)&Ws[r][c4 * 4] = *(const float4*)&W[(size_t)(kk + r) * 64 + c4 * 4];
        }
        *(float4*)&Hs[tr][tc * 4] = *(const float4*)&H[(size_t)(row0 + tr) * 256 + kk + tc * 4];
        __syncthreads();
#pragma unroll 8
        for (int k = 0; k < 64; k++) {
            float4 w4 = *(const float4*)&Ws[k][tc * 4];
            unsigned long long w01, w23, hp;
            asm("mov.b64 %0, {%1, %2};" : "=l"(w01) : "f"(w4.x), "f"(w4.y));
            asm("mov.b64 %0, {%1, %2};" : "=l"(w23) : "f"(w4.z), "f"(w4.w));
            float h = Hs[tr][k];
            asm("mov.b64 %0, {%1, %1};" : "=l"(hp) : "f"(h));
            asm("fma.rn.f32x2 %0, %1, %2, %0;" : "+l"(acc[0]) : "l"(hp), "l"(w01));
            asm("fma.rn.f32x2 %0, %1, %2, %0;" : "+l"(acc[1]) : "l"(hp), "l"(w23));
        }
        __syncthreads();
    }

    float v0 = __uint_as_float((uint32_t)acc[0]);
    float v1 = __uint_as_float((uint32_t)(acc[0] >> 32));
    float v2 = __uint_as_float((uint32_t)acc[1]);
    float v3 = __uint_as_float((uint32_t)(acc[1] >> 32));

    int i = row0 + tr;
    *(float4*)&g_Wh[(size_t)i * 64 + tc * 4] = make_float4(v0, v1, v2, v3);

    float p1 = v0 * __ldg(&a[tc * 4]) + v1 * __ldg(&a[tc * 4 + 1])
             + v2 * __ldg(&a[tc * 4 + 2]) + v3 * __ldg(&a[tc * 4 + 3]);
    float p2 = v0 * __ldg(&a[64 + tc * 4]) + v1 * __ldg(&a[64 + tc * 4 + 1])
             + v2 * __ldg(&a[64 + tc * 4 + 2]) + v3 * __ldg(&a[64 + tc * 4 + 3]);
#pragma unroll
    for (int off = 1; off < 16; off <<= 1) {
        p1 += __shfl_xor_sync(0xffffffffu, p1, off);
        p2 += __shfl_xor_sync(0xffffffffu, p2, off);
    }
    if (tc == 0) {
        g_e1[i] = p1;
        g_e2[i] = p2;
        g_E1[i] = __expf(p2);
        g_E2[i] = __expf(ALPHA * p2);
    }
}

// ---------------- kT: transpose + fp16 convert of Wh -> g_WhH ----------------
__global__ __launch_bounds__(256) void kT_split() {
    __shared__ float t[64][65];
    int tid = threadIdx.x;
    int j0 = blockIdx.x * 64;
#pragma unroll
    for (int q = 0; q < 4; q++) {
        int u = tid + q * 256;
        int r = u >> 4, c4 = u & 15;
        float4 vv = *(const float4*)&g_Wh[(size_t)(j0 + r) * 64 + c4 * 4];
        t[r][c4 * 4 + 0] = vv.x; t[r][c4 * 4 + 1] = vv.y;
        t[r][c4 * 4 + 2] = vv.z; t[r][c4 * 4 + 3] = vv.w;
    }
    __syncthreads();
    int c = tid >> 2;
    int jq = (tid & 3) * 16;
    uint32_t outv[8];
#pragma unroll
    for (int s = 0; s < 8; s++) {
        __half2 h = __floats2half2_rn(t[jq + s * 2 + 0][c], t[jq + s * 2 + 1][c]);
        outv[s] = *(uint32_t*)&h;
    }
    uint32_t* dst = &g_WhH[(size_t)c * (NV / 2) + ((j0 + jq) >> 1)];
    *(uint4*)dst = *(uint4*)&outv[0];
    *(uint4*)(dst + 4) = *(uint4*)&outv[4];
}

// ---------------- K2: per-row denominator ----------------
__global__ __launch_bounds__(256) void k2_denom() {
    __shared__ float sE1[NV];
    __shared__ float sE2[NV];
    __shared__ float red[8];
    int tid = threadIdx.x;
    int warp = tid >> 5, lane = tid & 31;
#pragma unroll
    for (int t = 0; t < 4; t++) {
        ((float4*)sE1)[tid + t * 256] = __ldg(&((const float4*)g_E1)[tid + t * 256]);
        ((float4*)sE2)[tid + t * 256] = __ldg(&((const float4*)g_E2)[tid + t * 256]);
    }
    float mx = -1e30f;
#pragma unroll
    for (int t = 0; t < 4; t++) {
        float4 v = __ldg(&((const float4*)g_e2)[tid + t * 256]);
        mx = fmaxf(fmaxf(mx, v.x), fmaxf(fmaxf(v.y, v.z), v.w));
    }
#pragma unroll
    for (int o = 16; o > 0; o >>= 1) mx = fmaxf(mx, __shfl_xor_sync(0xffffffffu, mx, o));
    if (lane == 0) red[warp] = mx;
    __syncthreads();
    float e2max = red[0];
#pragma unroll
    for (int w = 1; w < 8; w++) e2max = fmaxf(e2max, red[w]);

    int i = blockIdx.x * 8 + warp;
    float e1v = g_e1[i];
    float s = e1v + e2max;
    float m = s > 0.f ? s : ALPHA * s;
    float A = __expf(e1v - m);
    float B = __expf(ALPHA * e1v - m);
    float thE = __expf(-e1v);

    float d = 0.f;
#pragma unroll 8
    for (int t = 0; t < 32; t++) {
        int j = (lane + t * 32) * 4;
        float4 E1v = *(const float4*)&sE1[j];
        float4 E2v = *(const float4*)&sE2[j];
        d += (E1v.x > thE) ? A * E1v.x : B * E2v.x;
        d += (E1v.y > thE) ? A * E1v.y : B * E2v.y;
        d += (E1v.z > thE) ? A * E1v.z : B * E2v.z;
        d += (E1v.w > thE) ? A * E1v.w : B * E2v.w;
    }
#pragma unroll
    for (int o = 16; o > 0; o >>= 1) d += __shfl_xor_sync(0xffffffffu, d, o);
    if (lane == 0) {
        g_A[i] = A; g_B[i] = B; g_thE[i] = thE;
        g_dinv[i] = 1.f / d;
    }
}

// ---------------- A-fragment build ----------------
__device__ __forceinline__ uint32_t build_a(int ax, int ay,
                                            float e1x, float e1y,
                                            float e2x, float e2y,
                                            float Ai, float Bi, float th) {
    float w0 = (ax > 0) ? ((e1x > th) ? Ai * e1x : Bi * e2x) : 0.f;
    float w1 = (ay > 0) ? ((e1y > th) ? Ai * e1y : Bi * e2y) : 0.f;
    __half2 h = __floats2half2_rn(w0, w1);
    return *(uint32_t*)&h;
}

#define MMA_F16(c0, c1, c2, c3, a0, a1, a2, a3, b0, b1)                         \
    asm("mma.sync.aligned.m16n8k16.row.col.f32.f16.f16.f32 "                   \
        "{%0,%1,%2,%3}, {%4,%5,%6,%7}, {%8,%9}, {%0,%1,%2,%3};"                \
        : "+f"(c0), "+f"(c1), "+f"(c2), "+f"(c3)                               \
        : "r"(a0), "r"(a1), "r"(a2), "r"(a3), "r"(b0), "r"(b1))

#define CP_WAIT(n) asm volatile("cp.async.wait_group %0;" :: "n"(n) : "memory")

// ---------------- K3: masked GEMM, fp16 A & B, hoisted B, adj pipeline -------
// Grid 512 = 128 rb (32 i) x 4 jseg (1024 j). 4 warps/CTA, distinct 256-j
// quarters; adj cp.async depth-3 (warp-private); B fully hoisted per k-tile.
__global__ __launch_bounds__(128, 4) void k3_main(const int* __restrict__ adj) {
    __shared__ union {
        struct {
            int adjt[4][3][640];    // [warp][stage][row*20 + jj]
            float E1[4][256];
            float E2[4][256];
        } a;
        float red[4][32][68];
    } su;

    int tid = threadIdx.x;
    int warp = tid >> 5, lane = tid & 31;
    int gid = lane >> 2, tg = lane & 3;
    int rb = blockIdx.x >> 2;
    int jseg = blockIdx.x & 3;
    int jq = jseg * 1024 + warp * 256;
    int base = rb * 32;

    const int* adjw = adj + (size_t)base * NV + jq;
    int cp_row = lane >> 2;
    int cp_part = lane & 3;

    // prologue: adj tiles 0..2
#pragma unroll
    for (int kt = 0; kt < 3; kt++) {
#pragma unroll
        for (int q = 0; q < 4; q++) {
            int row = cp_row + q * 8;
            unsigned daddr = (unsigned)__cvta_generic_to_shared(
                &su.a.adjt[warp][kt][row * 20 + cp_part * 4]);
            const int* src = adjw + (size_t)row * NV + kt * 16 + cp_part * 4;
            asm volatile("cp.async.cg.shared.global [%0], [%1], 16;"
                         :: "r"(daddr), "l"(src) : "memory");
        }
        asm volatile("cp.async.commit_group;" ::: "memory");
    }

    // stage E for this warp's quarter
#pragma unroll
    for (int t = 0; t < 2; t++) {
        int idx = lane + t * 32;
        float4 v1 = __ldg(&((const float4*)(g_E1 + jq))[idx]);
        *(float4*)&su.a.E1[warp][idx * 4] = v1;
        float4 v2 = __ldg(&((const float4*)(g_E2 + jq))[idx]);
        *(float4*)&su.a.E2[warp][idx * 4] = v2;
    }
    __syncwarp();

    int r0 = base + gid, r1 = r0 + 8, r2 = r0 + 16, r3 = r0 + 24;
    float Ai0 = __ldg(&g_A[r0]), Bi0 = __ldg(&g_B[r0]), th0 = __ldg(&g_thE[r0]);
    float Ai1 = __ldg(&g_A[r1]), Bi1 = __ldg(&g_B[r1]), th1 = __ldg(&g_thE[r1]);
    float Ai2 = __ldg(&g_A[r2]), Bi2 = __ldg(&g_B[r2]), th2 = __ldg(&g_thE[r2]);
    float Ai3 = __ldg(&g_A[r3]), Bi3 = __ldg(&g_B[r3]), th3 = __ldg(&g_thE[r3]);

    float acc[2][8][4];
#pragma unroll
    for (int m = 0; m < 2; m++)
#pragma unroll
        for (int n = 0; n < 8; n++)
#pragma unroll
            for (int q = 0; q < 4; q++) acc[m][n][q] = 0.f;

#pragma unroll
    for (int kt = 0; kt < 16; ++kt) {
        int j0 = kt * 16 + tg * 2;
        int gj = jq + j0;

        // ---- hoist all B fragments for this k-tile (16 LDG.32, MLP) ----
        uint32_t b0[8], b1[8];
        size_t bj = (size_t)gj >> 1;
#pragma unroll
        for (int n = 0; n < 8; n++) {
            const uint32_t* bp = &g_WhH[(size_t)(n * 8 + gid) * (NV / 2) + bj];
            b0[n] = __ldg(bp);
            b1[n] = __ldg(bp + 4);
        }

        // wait for adj tile kt
        if (kt <= 13) { CP_WAIT(2); } else if (kt == 14) { CP_WAIT(1); } else { CP_WAIT(0); }
        __syncwarp();

        const int* sa = su.a.adjt[warp][kt % 3];
        int2 c0a = *(const int2*)&sa[gid * 20 + tg * 2];
        int2 c0b = *(const int2*)&sa[gid * 20 + tg * 2 + 8];
        int2 c1a = *(const int2*)&sa[(gid + 8) * 20 + tg * 2];
        int2 c1b = *(const int2*)&sa[(gid + 8) * 20 + tg * 2 + 8];
        int2 c2a = *(const int2*)&sa[(gid + 16) * 20 + tg * 2];
        int2 c2b = *(const int2*)&sa[(gid + 16) * 20 + tg * 2 + 8];
        int2 c3a = *(const int2*)&sa[(gid + 24) * 20 + tg * 2];
        int2 c3b = *(const int2*)&sa[(gid + 24) * 20 + tg * 2 + 8];

        float2 e10 = *(const float2*)&su.a.E1[warp][(j0 & 255)];
        float2 e18 = *(const float2*)&su.a.E1[warp][((j0 + 8) & 255)];
        float2 e20 = *(const float2*)&su.a.E2[warp][(j0 & 255)];
        float2 e28 = *(const float2*)&su.a.E2[warp][((j0 + 8) & 255)];

        uint32_t ah[2][4];
        ah[0][0] = build_a(c0a.x, c0a.y, e10.x, e10.y, e20.x, e20.y, Ai0, Bi0, th0);
        ah[0][1] = build_a(c1a.x, c1a.y, e10.x, e10.y, e20.x, e20.y, Ai1, Bi1, th1);
        ah[0][2] = build_a(c0b.x, c0b.y, e18.x, e18.y, e28.x, e28.y, Ai0, Bi0, th0);
        ah[0][3] = build_a(c1b.x, c1b.y, e18.x, e18.y, e28.x, e28.y, Ai1, Bi1, th1);
        ah[1][0] = build_a(c2a.x, c2a.y, e10.x, e10.y, e20.x, e20.y, Ai2, Bi2, th2);
        ah[1][1] = build_a(c3a.x, c3a.y, e10.x, e10.y, e20.x, e20.y, Ai3, Bi3, th3);
        ah[1][2] = build_a(c2b.x, c2b.y, e18.x, e18.y, e28.x, e28.y, Ai2, Bi2, th2);
        ah[1][3] = build_a(c3b.x, c3b.y, e18.x, e18.y, e28.x, e28.y, Ai3, Bi3, th3);

        // issue adj tile kt+3
        if (kt < 13) {
            int ktn = kt + 3;
#pragma unroll
            for (int q = 0; q < 4; q++) {
                int row = cp_row + q * 8;
                unsigned daddr = (unsigned)__cvta_generic_to_shared(
                    &su.a.adjt[warp][kt % 3][row * 20 + cp_part * 4]);
                const int* src = adjw + (size_t)row * NV + ktn * 16 + cp_part * 4;
                asm volatile("cp.async.cg.shared.global [%0], [%1], 16;"
                             :: "r"(daddr), "l"(src) : "memory");
            }
            asm volatile("cp.async.commit_group;" ::: "memory");
        }

        // ---- MMAs: 8 n-groups x 2 m-tiles x 1 ----
#pragma unroll
        for (int n = 0; n < 8; n++) {
#pragma unroll
            for (int m = 0; m < 2; m++) {
                MMA_F16(acc[m][n][0], acc[m][n][1], acc[m][n][2], acc[m][n][3],
                        ah[m][0], ah[m][1], ah[m][2], ah[m][3], b0[n], b1[n]);
            }
        }
    }

    // ---- cross-warp reduction ----
    __syncthreads();
    float* sw = &su.red[warp][0][0];
#pragma unroll
    for (int n = 0; n < 8; n++) {
        int c = n * 8 + tg * 2;
        *(float2*)&sw[gid * 68 + c]        = make_float2(acc[0][n][0], acc[0][n][1]);
        *(float2*)&sw[(gid + 8) * 68 + c]  = make_float2(acc[0][n][2], acc[0][n][3]);
        *(float2*)&sw[(gid + 16) * 68 + c] = make_float2(acc[1][n][0], acc[1][n][1]);
        *(float2*)&sw[(gid + 24) * 68 + c] = make_float2(acc[1][n][2], acc[1][n][3]);
    }
    __syncthreads();

    float* dst = g_part[jseg];
#pragma unroll
    for (int q = 0; q < 4; q++) {
        int v = tid + q * 128;
        int row = v >> 4;
        int col = (v & 15) * 4;
        float4 s0 = *(const float4*)&su.red[0][row][col];
        float4 s1 = *(const float4*)&su.red[1][row][col];
        float4 s2 = *(const float4*)&su.red[2][row][col];
        float4 s3 = *(const float4*)&su.red[3][row][col];
        float4 r;
        r.x = s0.x + s1.x + s2.x + s3.x;
        r.y = s0.y + s1.y + s2.y + s3.y;
        r.z = s0.z + s1.z + s2.z + s3.z;
        r.w = s0.w + s1.w + s2.w + s3.w;
        *(float4*)&dst[(size_t)(base + row) * 64 + col] = r;
    }
}

// ---------------- K4: combine 4 partials, scale, ELU ----------------
__global__ __launch_bounds__(256) void k4_out(float* __restrict__ out) {
    int v4 = blockIdx.x * 256 + threadIdx.x;
    float4 s = __ldg(&((const float4*)g_part[0])[v4]);
#pragma unroll
    for (int p = 1; p < 4; p++) {
        float4 t = __ldg(&((const float4*)g_part[p])[v4]);
        s.x += t.x; s.y += t.y; s.z += t.z; s.w += t.w;
    }
    int i = v4 >> 4;
    float di = g_dinv[i];
    s.x *= di; s.y *= di; s.z *= di; s.w *= di;
    s.x = s.x > 0.f ? s.x : (__expf(s.x) - 1.f);
    s.y = s.y > 0.f ? s.y : (__expf(s.y) - 1.f);
    s.z = s.z > 0.f ? s.z : (__expf(s.z) - 1.f);
    s.w = s.w > 0.f ? s.w : (__expf(s.w) - 1.f);
    ((float4*)out)[v4] = s;
}

// ---------------- launch ----------------
extern "C" void kernel_launch(void* const* d_in, const int* in_sizes, int n_in,
                              void* d_out, int out_size) {
    const float* H = (const float*)d_in[0];
    const int* adj = (const int*)d_in[1];
    const float* W = (const float*)d_in[2];
    const float* a = (const float*)d_in[3];
    float* out = (float*)d_out;

    k1_wh<<<256, 256>>>(H, W, a);
    kT_split<<<64, 256>>>();
    k2_denom<<<512, 256>>>();
    k3_main<<<512, 128>>>(adj);
    k4_out<<<256, 256>>>(out);
}

// round 14
// speedup vs baseline: 1.7016x; 1.2173x over previous
#include <cuda_runtime.h>
#include <cuda_fp16.h>
#include <cstdint>

#define NV 4096
#define ALPHA 0.2f

// ---------------- device scratch ----------------
__device__ float g_Wh[NV * 64];
__device__ float g_e1[NV], g_e2[NV];
__device__ float g_E1[NV], g_E2[NV];
__device__ float g_A[NV], g_B[NV], g_thE[NV], g_dinv[NV];
__device__ float g_part[4][NV * 64];
// fragment-ordered B: [jt 0..255][n 0..7][reg 0..1][lane 0..31], u32 = f16x2
__device__ uint32_t g_WhB[256 * 512];

// ---------------- K1: Wh = H@W + e1/e2 + E1/E2 ----------------
__global__ __launch_bounds__(256) void k1_wh(const float* __restrict__ H,
                                             const float* __restrict__ W,
                                             const float* __restrict__ a) {
    __shared__ float Hs[16][68];
    __shared__ float Ws[64][64];
    int tid = threadIdx.x;
    int tr = tid >> 4;
    int tc = tid & 15;
    int row0 = blockIdx.x * 16;

    unsigned long long acc[2] = {0ull, 0ull};

    for (int kk = 0; kk < 256; kk += 64) {
#pragma unroll
        for (int t = 0; t < 4; t++) {
            int u = tid + t * 256;
            int r = u >> 4, c4 = u & 15;
            *(float4*)&Ws[r][c4 * 4] = *(const float4*)&W[(size_t)(kk + r) * 64 + c4 * 4];
        }
        *(float4*)&Hs[tr][tc * 4] = *(const float4*)&H[(size_t)(row0 + tr) * 256 + kk + tc * 4];
        __syncthreads();
#pragma unroll 8
        for (int k = 0; k < 64; k++) {
            float4 w4 = *(const float4*)&Ws[k][tc * 4];
            unsigned long long w01, w23, hp;
            asm("mov.b64 %0, {%1, %2};" : "=l"(w01) : "f"(w4.x), "f"(w4.y));
            asm("mov.b64 %0, {%1, %2};" : "=l"(w23) : "f"(w4.z), "f"(w4.w));
            float h = Hs[tr][k];
            asm("mov.b64 %0, {%1, %1};" : "=l"(hp) : "f"(h));
            asm("fma.rn.f32x2 %0, %1, %2, %0;" : "+l"(acc[0]) : "l"(hp), "l"(w01));
            asm("fma.rn.f32x2 %0, %1, %2, %0;" : "+l"(acc[1]) : "l"(hp), "l"(w23));
        }
        __syncthreads();
    }

    float v0 = __uint_as_float((uint32_t)acc[0]);
    float v1 = __uint_as_float((uint32_t)(acc[0] >> 32));
    float v2 = __uint_as_float((uint32_t)acc[1]);
    float v3 = __uint_as_float((uint32_t)(acc[1] >> 32));

    int i = row0 + tr;
    *(float4*)&g_Wh[(size_t)i * 64 + tc * 4] = make_float4(v0, v1, v2, v3);

    float p1 = v0 * __ldg(&a[tc * 4]) + v1 * __ldg(&a[tc * 4 + 1])
             + v2 * __ldg(&a[tc * 4 + 2]) + v3 * __ldg(&a[tc * 4 + 3]);
    float p2 = v0 * __ldg(&a[64 + tc * 4]) + v1 * __ldg(&a[64 + tc * 4 + 1])
             + v2 * __ldg(&a[64 + tc * 4 + 2]) + v3 * __ldg(&a[64 + tc * 4 + 3]);
#pragma unroll
    for (int off = 1; off < 16; off <<= 1) {
        p1 += __shfl_xor_sync(0xffffffffu, p1, off);
        p2 += __shfl_xor_sync(0xffffffffu, p2, off);
    }
    if (tc == 0) {
        g_e1[i] = p1;
        g_e2[i] = p2;
        g_E1[i] = __expf(p2);
        g_E2[i] = __expf(ALPHA * p2);
    }
}

// ---------------- kT: Wh -> fragment-ordered fp16 B (g_WhB) ------------------
// Block handles 64 j rows (4 j-tiles). Stage Wh[64][64] in smem, then each
// thread emits 8 consecutive fragment u32s.
__global__ __launch_bounds__(256) void kT_split() {
    __shared__ float t[64][65];
    int tid = threadIdx.x;
    int j0 = blockIdx.x * 64;
#pragma unroll
    for (int q = 0; q < 4; q++) {
        int u = tid + q * 256;
        int r = u >> 4, c4 = u & 15;
        float4 vv = *(const float4*)&g_Wh[(size_t)(j0 + r) * 64 + c4 * 4];
        t[r][c4 * 4 + 0] = vv.x; t[r][c4 * 4 + 1] = vv.y;
        t[r][c4 * 4 + 2] = vv.z; t[r][c4 * 4 + 3] = vv.w;
    }
    __syncthreads();
    uint32_t outv[8];
#pragma unroll
    for (int q = 0; q < 8; q++) {
        int idx = tid * 8 + q;           // 0..2047
        int lane = idx & 31;
        int reg = (idx >> 5) & 1;
        int n = (idx >> 6) & 7;
        int jtl = idx >> 9;              // 0..3
        int gid = lane >> 2, tg = lane & 3;
        int jr = jtl * 16 + tg * 2 + reg * 8;
        int c = n * 8 + gid;
        __half2 h = __floats2half2_rn(t[jr][c], t[jr + 1][c]);
        outv[q] = *(uint32_t*)&h;
    }
    uint32_t* dst = &g_WhB[(size_t)(j0 >> 4) * 512 + tid * 8];
    *(uint4*)dst = *(uint4*)&outv[0];
    *(uint4*)(dst + 4) = *(uint4*)&outv[4];
}

// ---------------- K2: per-row denominator ----------------
__global__ __launch_bounds__(256) void k2_denom() {
    __shared__ float sE1[NV];
    __shared__ float sE2[NV];
    __shared__ float red[8];
    int tid = threadIdx.x;
    int warp = tid >> 5, lane = tid & 31;
#pragma unroll
    for (int t = 0; t < 4; t++) {
        ((float4*)sE1)[tid + t * 256] = __ldg(&((const float4*)g_E1)[tid + t * 256]);
        ((float4*)sE2)[tid + t * 256] = __ldg(&((const float4*)g_E2)[tid + t * 256]);
    }
    float mx = -1e30f;
#pragma unroll
    for (int t = 0; t < 4; t++) {
        float4 v = __ldg(&((const float4*)g_e2)[tid + t * 256]);
        mx = fmaxf(fmaxf(mx, v.x), fmaxf(fmaxf(v.y, v.z), v.w));
    }
#pragma unroll
    for (int o = 16; o > 0; o >>= 1) mx = fmaxf(mx, __shfl_xor_sync(0xffffffffu, mx, o));
    if (lane == 0) red[warp] = mx;
    __syncthreads();
    float e2max = red[0];
#pragma unroll
    for (int w = 1; w < 8; w++) e2max = fmaxf(e2max, red[w]);

    int i = blockIdx.x * 8 + warp;
    float e1v = g_e1[i];
    float s = e1v + e2max;
    float m = s > 0.f ? s : ALPHA * s;
    float A = __expf(e1v - m);
    float B = __expf(ALPHA * e1v - m);
    float thE = __expf(-e1v);

    float d = 0.f;
#pragma unroll 8
    for (int t = 0; t < 32; t++) {
        int j = (lane + t * 32) * 4;
        float4 E1v = *(const float4*)&sE1[j];
        float4 E2v = *(const float4*)&sE2[j];
        d += (E1v.x > thE) ? A * E1v.x : B * E2v.x;
        d += (E1v.y > thE) ? A * E1v.y : B * E2v.y;
        d += (E1v.z > thE) ? A * E1v.z : B * E2v.z;
        d += (E1v.w > thE) ? A * E1v.w : B * E2v.w;
    }
#pragma unroll
    for (int o = 16; o > 0; o >>= 1) d += __shfl_xor_sync(0xffffffffu, d, o);
    if (lane == 0) {
        g_A[i] = A; g_B[i] = B; g_thE[i] = thE;
        g_dinv[i] = 1.f / d;
    }
}

// ---------------- A-fragment build ----------------
__device__ __forceinline__ uint32_t build_a(int ax, int ay,
                                            float e1x, float e1y,
                                            float e2x, float e2y,
                                            float Ai, float Bi, float th) {
    float w0 = (ax > 0) ? ((e1x > th) ? Ai * e1x : Bi * e2x) : 0.f;
    float w1 = (ay > 0) ? ((e1y > th) ? Ai * e1y : Bi * e2y) : 0.f;
    __half2 h = __floats2half2_rn(w0, w1);
    return *(uint32_t*)&h;
}

#define MMA_F16(c0, c1, c2, c3, a0, a1, a2, a3, b0, b1)                         \
    asm("mma.sync.aligned.m16n8k16.row.col.f32.f16.f16.f32 "                   \
        "{%0,%1,%2,%3}, {%4,%5,%6,%7}, {%8,%9}, {%0,%1,%2,%3};"                \
        : "+f"(c0), "+f"(c1), "+f"(c2), "+f"(c3)                               \
        : "r"(a0), "r"(a1), "r"(a2), "r"(a3), "r"(b0), "r"(b1))

#define CP_WAIT(n) asm volatile("cp.async.wait_group %0;" :: "n"(n) : "memory")

// ---------------- K3: masked GEMM, fragment-ordered B, adj pipeline ----------
__global__ __launch_bounds__(128, 4) void k3_main(const int* __restrict__ adj) {
    __shared__ union {
        struct {
            int adjt[4][3][640];
            float E1[4][256];
            float E2[4][256];
        } a;
        float red[4][32][68];
    } su;

    int tid = threadIdx.x;
    int warp = tid >> 5, lane = tid & 31;
    int gid = lane >> 2, tg = lane & 3;
    int rb = blockIdx.x >> 2;
    int jseg = blockIdx.x & 3;
    int jq = jseg * 1024 + warp * 256;
    int base = rb * 32;

    const int* adjw = adj + (size_t)base * NV + jq;
    int cp_row = lane >> 2;
    int cp_part = lane & 3;

    // prologue: adj tiles 0..2
#pragma unroll
    for (int kt = 0; kt < 3; kt++) {
#pragma unroll
        for (int q = 0; q < 4; q++) {
            int row = cp_row + q * 8;
            unsigned daddr = (unsigned)__cvta_generic_to_shared(
                &su.a.adjt[warp][kt][row * 20 + cp_part * 4]);
            const int* src = adjw + (size_t)row * NV + kt * 16 + cp_part * 4;
            asm volatile("cp.async.cg.shared.global [%0], [%1], 16;"
                         :: "r"(daddr), "l"(src) : "memory");
        }
        asm volatile("cp.async.commit_group;" ::: "memory");
    }

    // stage E for this warp's quarter
#pragma unroll
    for (int t = 0; t < 2; t++) {
        int idx = lane + t * 32;
        float4 v1 = __ldg(&((const float4*)(g_E1 + jq))[idx]);
        *(float4*)&su.a.E1[warp][idx * 4] = v1;
        float4 v2 = __ldg(&((const float4*)(g_E2 + jq))[idx]);
        *(float4*)&su.a.E2[warp][idx * 4] = v2;
    }
    __syncwarp();

    int r0 = base + gid, r1 = r0 + 8, r2 = r0 + 16, r3 = r0 + 24;
    float Ai0 = __ldg(&g_A[r0]), Bi0 = __ldg(&g_B[r0]), th0 = __ldg(&g_thE[r0]);
    float Ai1 = __ldg(&g_A[r1]), Bi1 = __ldg(&g_B[r1]), th1 = __ldg(&g_thE[r1]);
    float Ai2 = __ldg(&g_A[r2]), Bi2 = __ldg(&g_B[r2]), th2 = __ldg(&g_thE[r2]);
    float Ai3 = __ldg(&g_A[r3]), Bi3 = __ldg(&g_B[r3]), th3 = __ldg(&g_thE[r3]);

    float acc[2][8][4];
#pragma unroll
    for (int m = 0; m < 2; m++)
#pragma unroll
        for (int n = 0; n < 8; n++)
#pragma unroll
            for (int q = 0; q < 4; q++) acc[m][n][q] = 0.f;

    int jt0 = jq >> 4;   // first global j-tile of this warp

#pragma unroll
    for (int kt = 0; kt < 16; ++kt) {
        // ---- hoisted, fully-coalesced B fragment loads ----
        uint32_t b0[8], b1[8];
        const uint32_t* bb = g_WhB + (size_t)(jt0 + kt) * 512 + lane;
#pragma unroll
        for (int n = 0; n < 8; n++) {
            b0[n] = __ldg(bb + n * 64);
            b1[n] = __ldg(bb + n * 64 + 32);
        }

        // wait for adj tile kt
        if (kt <= 13) { CP_WAIT(2); } else if (kt == 14) { CP_WAIT(1); } else { CP_WAIT(0); }
        __syncwarp();

        const int* sa = su.a.adjt[warp][kt % 3];
        int2 c0a = *(const int2*)&sa[gid * 20 + tg * 2];
        int2 c0b = *(const int2*)&sa[gid * 20 + tg * 2 + 8];
        int2 c1a = *(const int2*)&sa[(gid + 8) * 20 + tg * 2];
        int2 c1b = *(const int2*)&sa[(gid + 8) * 20 + tg * 2 + 8];
        int2 c2a = *(const int2*)&sa[(gid + 16) * 20 + tg * 2];
        int2 c2b = *(const int2*)&sa[(gid + 16) * 20 + tg * 2 + 8];
        int2 c3a = *(const int2*)&sa[(gid + 24) * 20 + tg * 2];
        int2 c3b = *(const int2*)&sa[(gid + 24) * 20 + tg * 2 + 8];

        int j0 = kt * 16 + tg * 2;
        float2 e10 = *(const float2*)&su.a.E1[warp][(j0 & 255)];
        float2 e18 = *(const float2*)&su.a.E1[warp][((j0 + 8) & 255)];
        float2 e20 = *(const float2*)&su.a.E2[warp][(j0 & 255)];
        float2 e28 = *(const float2*)&su.a.E2[warp][((j0 + 8) & 255)];

        uint32_t ah[2][4];
        ah[0][0] = build_a(c0a.x, c0a.y, e10.x, e10.y, e20.x, e20.y, Ai0, Bi0, th0);
        ah[0][1] = build_a(c1a.x, c1a.y, e10.x, e10.y, e20.x, e20.y, Ai1, Bi1, th1);
        ah[0][2] = build_a(c0b.x, c0b.y, e18.x, e18.y, e28.x, e28.y, Ai0, Bi0, th0);
        ah[0][3] = build_a(c1b.x, c1b.y, e18.x, e18.y, e28.x, e28.y, Ai1, Bi1, th1);
        ah[1][0] = build_a(c2a.x, c2a.y, e10.x, e10.y, e20.x, e20.y, Ai2, Bi2, th2);
        ah[1][1] = build_a(c3a.x, c3a.y, e10.x, e10.y, e20.x, e20.y, Ai3, Bi3, th3);
        ah[1][2] = build_a(c2b.x, c2b.y, e18.x, e18.y, e28.x, e28.y, Ai2, Bi2, th2);
        ah[1][3] = build_a(c3b.x, c3b.y, e18.x, e18.y, e28.x, e28.y, Ai3, Bi3, th3);

        // issue adj tile kt+3
        if (kt < 13) {
            int ktn = kt + 3;
#pragma unroll
            for (int q = 0; q < 4; q++) {
                int row = cp_row + q * 8;
                unsigned daddr = (unsigned)__cvta_generic_to_shared(
                    &su.a.adjt[warp][kt % 3][row * 20 + cp_part * 4]);
                const int* src = adjw + (size_t)row * NV + ktn * 16 + cp_part * 4;
                asm volatile("cp.async.cg.shared.global [%0], [%1], 16;"
                             :: "r"(daddr), "l"(src) : "memory");
            }
            asm volatile("cp.async.commit_group;" ::: "memory");
        }

        // ---- MMAs ----
#pragma unroll
        for (int n = 0; n < 8; n++) {
#pragma unroll
            for (int m = 0; m < 2; m++) {
                MMA_F16(acc[m][n][0], acc[m][n][1], acc[m][n][2], acc[m][n][3],
                        ah[m][0], ah[m][1], ah[m][2], ah[m][3], b0[n], b1[n]);
            }
        }
    }

    // ---- cross-warp reduction ----
    __syncthreads();
    float* sw = &su.red[warp][0][0];
#pragma unroll
    for (int n = 0; n < 8; n++) {
        int c = n * 8 + tg * 2;
        *(float2*)&sw[gid * 68 + c]        = make_float2(acc[0][n][0], acc[0][n][1]);
        *(float2*)&sw[(gid + 8) * 68 + c]  = make_float2(acc[0][n][2], acc[0][n][3]);
        *(float2*)&sw[(gid + 16) * 68 + c] = make_float2(acc[1][n][0], acc[1][n][1]);
        *(float2*)&sw[(gid + 24) * 68 + c] = make_float2(acc[1][n][2], acc[1][n][3]);
    }
    __syncthreads();

    float* dst = g_part[jseg];
#pragma unroll
    for (int q = 0; q < 4; q++) {
        int v = tid + q * 128;
        int row = v >> 4;
        int col = (v & 15) * 4;
        float4 s0 = *(const float4*)&su.red[0][row][col];
        float4 s1 = *(const float4*)&su.red[1][row][col];
        float4 s2 = *(const float4*)&su.red[2][row][col];
        float4 s3 = *(const float4*)&su.red[3][row][col];
        float4 r;
        r.x = s0.x + s1.x + s2.x + s3.x;
        r.y = s0.y + s1.y + s2.y + s3.y;
        r.z = s0.z + s1.z + s2.z + s3.z;
        r.w = s0.w + s1.w + s2.w + s3.w;
        *(float4*)&dst[(size_t)(base + row) * 64 + col] = r;
    }
}

// ---------------- K4: combine 4 partials, scale, ELU ----------------
__global__ __launch_bounds__(256) void k4_out(float* __restrict__ out) {
    int v4 = blockIdx.x * 256 + threadIdx.x;
    float4 s = __ldg(&((const float4*)g_part[0])[v4]);
#pragma unroll
    for (int p = 1; p < 4; p++) {
        float4 t = __ldg(&((const float4*)g_part[p])[v4]);
        s.x += t.x; s.y += t.y; s.z += t.z; s.w += t.w;
    }
    int i = v4 >> 4;
    float di = g_dinv[i];
    s.x *= di; s.y *= di; s.z *= di; s.w *= di;
    s.x = s.x > 0.f ? s.x : (__expf(s.x) - 1.f);
    s.y = s.y > 0.f ? s.y : (__expf(s.y) - 1.f);
    s.z = s.z > 0.f ? s.z : (__expf(s.z) - 1.f);
    s.w = s.w > 0.f ? s.w : (__expf(s.w) - 1.f);
    ((float4*)out)[v4] = s;
}

// ---------------- launch ----------------
extern "C" void kernel_launch(void* const* d_in, const int* in_sizes, int n_in,
                              void* d_out, int out_size) {
    const float* H = (const float*)d_in[0];
    const int* adj = (const int*)d_in[1];
    const float* W = (const float*)d_in[2];
    const float* a = (const float*)d_in[3];
    float* out = (float*)d_out;

    k1_wh<<<256, 256>>>(H, W, a);
    kT_split<<<64, 256>>>();
    k2_denom<<<512, 256>>>();
    k3_main<<<512, 128>>>(adj);
    k4_out<<<256, 256>>>(out);
}

// round 15
// speedup vs baseline: 1.7645x; 1.0370x over previous
#include <cuda_runtime.h>
#include <cuda_fp16.h>
#include <cstdint>

#define NV 4096
#define ALPHA 0.2f

// ---------------- device scratch ----------------
__device__ float g_e1[NV], g_e2[NV];
__device__ float g_E1[NV], g_E2[NV];
__device__ float g_A[NV], g_B[NV], g_thE[NV], g_dinv[NV];
__device__ float g_part[4][NV * 64];
// fragment-ordered B: [jt 0..255][n 0..7][reg 0..1][lane 0..31], u32 = f16x2
__device__ uint32_t g_WhB[256 * 512];
__device__ int g_cnt[128];

// ---------------- K1: Wh = H@W + e1/e2 + E1/E2 + fragment emit ---------------
// Block = 16 rows = one j-tile; emits g_WhB[jt] directly (kT fused).
__global__ __launch_bounds__(256) void k1_wh(const float* __restrict__ H,
                                             const float* __restrict__ W,
                                             const float* __restrict__ a) {
    __shared__ float Hs[16][68];
    __shared__ float Ws[64][64];
    __shared__ float t[16][68];
    int tid = threadIdx.x;
    int tr = tid >> 4;
    int tc = tid & 15;
    int row0 = blockIdx.x * 16;

    unsigned long long acc[2] = {0ull, 0ull};

    for (int kk = 0; kk < 256; kk += 64) {
#pragma unroll
        for (int q = 0; q < 4; q++) {
            int u = tid + q * 256;
            int r = u >> 4, c4 = u & 15;
            *(float4*)&Ws[r][c4 * 4] = *(const float4*)&W[(size_t)(kk + r) * 64 + c4 * 4];
        }
        *(float4*)&Hs[tr][tc * 4] = *(const float4*)&H[(size_t)(row0 + tr) * 256 + kk + tc * 4];
        __syncthreads();
#pragma unroll 8
        for (int k = 0; k < 64; k++) {
            float4 w4 = *(const float4*)&Ws[k][tc * 4];
            unsigned long long w01, w23, hp;
            asm("mov.b64 %0, {%1, %2};" : "=l"(w01) : "f"(w4.x), "f"(w4.y));
            asm("mov.b64 %0, {%1, %2};" : "=l"(w23) : "f"(w4.z), "f"(w4.w));
            float h = Hs[tr][k];
            asm("mov.b64 %0, {%1, %1};" : "=l"(hp) : "f"(h));
            asm("fma.rn.f32x2 %0, %1, %2, %0;" : "+l"(acc[0]) : "l"(hp), "l"(w01));
            asm("fma.rn.f32x2 %0, %1, %2, %0;" : "+l"(acc[1]) : "l"(hp), "l"(w23));
        }
        __syncthreads();
    }

    float v0 = __uint_as_float((uint32_t)acc[0]);
    float v1 = __uint_as_float((uint32_t)(acc[0] >> 32));
    float v2 = __uint_as_float((uint32_t)acc[1]);
    float v3 = __uint_as_float((uint32_t)(acc[1] >> 32));

    // stage Wh tile for fragment emission
    *(float4*)&t[tr][tc * 4] = make_float4(v0, v1, v2, v3);

    int i = row0 + tr;
    float p1 = v0 * __ldg(&a[tc * 4]) + v1 * __ldg(&a[tc * 4 + 1])
             + v2 * __ldg(&a[tc * 4 + 2]) + v3 * __ldg(&a[tc * 4 + 3]);
    float p2 = v0 * __ldg(&a[64 + tc * 4]) + v1 * __ldg(&a[64 + tc * 4 + 1])
             + v2 * __ldg(&a[64 + tc * 4 + 2]) + v3 * __ldg(&a[64 + tc * 4 + 3]);
#pragma unroll
    for (int off = 1; off < 16; off <<= 1) {
        p1 += __shfl_xor_sync(0xffffffffu, p1, off);
        p2 += __shfl_xor_sync(0xffffffffu, p2, off);
    }
    if (tc == 0) {
        g_e1[i] = p1;
        g_e2[i] = p2;
        g_E1[i] = __expf(p2);
        g_E2[i] = __expf(ALPHA * p2);
    }
    __syncthreads();

    // emit fp16 B fragments for this j-tile (layout matches k3 consumption)
    int jt = blockIdx.x;
#pragma unroll
    for (int q = 0; q < 2; q++) {
        int idx = tid + q * 256;          // 0..511
        int lane = idx & 31;
        int reg = (idx >> 5) & 1;
        int n = idx >> 6;
        int gid2 = lane >> 2, tg2 = lane & 3;
        int jr = tg2 * 2 + reg * 8;
        int c = n * 8 + gid2;
        __half2 h = __floats2half2_rn(t[jr][c], t[jr + 1][c]);
        g_WhB[(size_t)jt * 512 + idx] = *(uint32_t*)&h;
    }
}

// ---------------- K2: per-row denominator (+ counter reset) ----------------
__global__ __launch_bounds__(256) void k2_denom() {
    __shared__ float sE1[NV];
    __shared__ float sE2[NV];
    __shared__ float red[8];
    int tid = threadIdx.x;
    int warp = tid >> 5, lane = tid & 31;
    if (blockIdx.x < 128 && tid == 0) g_cnt[blockIdx.x] = 0;
#pragma unroll
    for (int t = 0; t < 4; t++) {
        ((float4*)sE1)[tid + t * 256] = __ldg(&((const float4*)g_E1)[tid + t * 256]);
        ((float4*)sE2)[tid + t * 256] = __ldg(&((const float4*)g_E2)[tid + t * 256]);
    }
    float mx = -1e30f;
#pragma unroll
    for (int t = 0; t < 4; t++) {
        float4 v = __ldg(&((const float4*)g_e2)[tid + t * 256]);
        mx = fmaxf(fmaxf(mx, v.x), fmaxf(fmaxf(v.y, v.z), v.w));
    }
#pragma unroll
    for (int o = 16; o > 0; o >>= 1) mx = fmaxf(mx, __shfl_xor_sync(0xffffffffu, mx, o));
    if (lane == 0) red[warp] = mx;
    __syncthreads();
    float e2max = red[0];
#pragma unroll
    for (int w = 1; w < 8; w++) e2max = fmaxf(e2max, red[w]);

    int i = blockIdx.x * 8 + warp;
    float e1v = g_e1[i];
    float s = e1v + e2max;
    float m = s > 0.f ? s : ALPHA * s;
    float A = __expf(e1v - m);
    float B = __expf(ALPHA * e1v - m);
    float thE = __expf(-e1v);

    float d = 0.f;
#pragma unroll 8
    for (int t = 0; t < 32; t++) {
        int j = (lane + t * 32) * 4;
        float4 E1v = *(const float4*)&sE1[j];
        float4 E2v = *(const float4*)&sE2[j];
        d += (E1v.x > thE) ? A * E1v.x : B * E2v.x;
        d += (E1v.y > thE) ? A * E1v.y : B * E2v.y;
        d += (E1v.z > thE) ? A * E1v.z : B * E2v.z;
        d += (E1v.w > thE) ? A * E1v.w : B * E2v.w;
    }
#pragma unroll
    for (int o = 16; o > 0; o >>= 1) d += __shfl_xor_sync(0xffffffffu, d, o);
    if (lane == 0) {
        g_A[i] = A; g_B[i] = B; g_thE[i] = thE;
        g_dinv[i] = 1.f / d;
    }
}

// ---------------- A-fragment build ----------------
__device__ __forceinline__ uint32_t build_a(int ax, int ay,
                                            float e1x, float e1y,
                                            float e2x, float e2y,
                                            float Ai, float Bi, float th) {
    float w0 = (ax > 0) ? ((e1x > th) ? Ai * e1x : Bi * e2x) : 0.f;
    float w1 = (ay > 0) ? ((e1y > th) ? Ai * e1y : Bi * e2y) : 0.f;
    __half2 h = __floats2half2_rn(w0, w1);
    return *(uint32_t*)&h;
}

#define MMA_F16(c0, c1, c2, c3, a0, a1, a2, a3, b0, b1)                         \
    asm("mma.sync.aligned.m16n8k16.row.col.f32.f16.f16.f32 "                   \
        "{%0,%1,%2,%3}, {%4,%5,%6,%7}, {%8,%9}, {%0,%1,%2,%3};"                \
        : "+f"(c0), "+f"(c1), "+f"(c2), "+f"(c3)                               \
        : "r"(a0), "r"(a1), "r"(a2), "r"(a3), "r"(b0), "r"(b1))

#define CP_WAIT(n) asm volatile("cp.async.wait_group %0;" :: "n"(n) : "memory")

// ---------------- K3: masked GEMM + fused final reduce/ELU -------------------
__global__ __launch_bounds__(128, 4) void k3_main(const int* __restrict__ adj,
                                                  float* __restrict__ out) {
    __shared__ union {
        struct {
            int adjt[4][3][640];
            float E1[4][256];
            float E2[4][256];
        } a;
        float red[4][32][68];
    } su;
    __shared__ int s_last;

    int tid = threadIdx.x;
    int warp = tid >> 5, lane = tid & 31;
    int gid = lane >> 2, tg = lane & 3;
    int rb = blockIdx.x >> 2;
    int jseg = blockIdx.x & 3;
    int jq = jseg * 1024 + warp * 256;
    int base = rb * 32;

    const int* adjw = adj + (size_t)base * NV + jq;
    int cp_row = lane >> 2;
    int cp_part = lane & 3;

    // prologue: adj tiles 0..2
#pragma unroll
    for (int kt = 0; kt < 3; kt++) {
#pragma unroll
        for (int q = 0; q < 4; q++) {
            int row = cp_row + q * 8;
            unsigned daddr = (unsigned)__cvta_generic_to_shared(
                &su.a.adjt[warp][kt][row * 20 + cp_part * 4]);
            const int* src = adjw + (size_t)row * NV + kt * 16 + cp_part * 4;
            asm volatile("cp.async.cg.shared.global [%0], [%1], 16;"
                         :: "r"(daddr), "l"(src) : "memory");
        }
        asm volatile("cp.async.commit_group;" ::: "memory");
    }

    // stage E for this warp's quarter
#pragma unroll
    for (int t = 0; t < 2; t++) {
        int idx = lane + t * 32;
        float4 v1 = __ldg(&((const float4*)(g_E1 + jq))[idx]);
        *(float4*)&su.a.E1[warp][idx * 4] = v1;
        float4 v2 = __ldg(&((const float4*)(g_E2 + jq))[idx]);
        *(float4*)&su.a.E2[warp][idx * 4] = v2;
    }
    __syncwarp();

    int r0 = base + gid, r1 = r0 + 8, r2 = r0 + 16, r3 = r0 + 24;
    float Ai0 = __ldg(&g_A[r0]), Bi0 = __ldg(&g_B[r0]), th0 = __ldg(&g_thE[r0]);
    float Ai1 = __ldg(&g_A[r1]), Bi1 = __ldg(&g_B[r1]), th1 = __ldg(&g_thE[r1]);
    float Ai2 = __ldg(&g_A[r2]), Bi2 = __ldg(&g_B[r2]), th2 = __ldg(&g_thE[r2]);
    float Ai3 = __ldg(&g_A[r3]), Bi3 = __ldg(&g_B[r3]), th3 = __ldg(&g_thE[r3]);

    float acc[2][8][4];
#pragma unroll
    for (int m = 0; m < 2; m++)
#pragma unroll
        for (int n = 0; n < 8; n++)
#pragma unroll
            for (int q = 0; q < 4; q++) acc[m][n][q] = 0.f;

    int jt0 = jq >> 4;

#pragma unroll
    for (int kt = 0; kt < 16; ++kt) {
        // hoisted coalesced B fragment loads
        uint32_t b0[8], b1[8];
        const uint32_t* bb = g_WhB + (size_t)(jt0 + kt) * 512 + lane;
#pragma unroll
        for (int n = 0; n < 8; n++) {
            b0[n] = __ldg(bb + n * 64);
            b1[n] = __ldg(bb + n * 64 + 32);
        }

        if (kt <= 13) { CP_WAIT(2); } else if (kt == 14) { CP_WAIT(1); } else { CP_WAIT(0); }
        __syncwarp();

        const int* sa = su.a.adjt[warp][kt % 3];
        int2 c0a = *(const int2*)&sa[gid * 20 + tg * 2];
        int2 c0b = *(const int2*)&sa[gid * 20 + tg * 2 + 8];
        int2 c1a = *(const int2*)&sa[(gid + 8) * 20 + tg * 2];
        int2 c1b = *(const int2*)&sa[(gid + 8) * 20 + tg * 2 + 8];
        int2 c2a = *(const int2*)&sa[(gid + 16) * 20 + tg * 2];
        int2 c2b = *(const int2*)&sa[(gid + 16) * 20 + tg * 2 + 8];
        int2 c3a = *(const int2*)&sa[(gid + 24) * 20 + tg * 2];
        int2 c3b = *(const int2*)&sa[(gid + 24) * 20 + tg * 2 + 8];

        int j0 = kt * 16 + tg * 2;
        float2 e10 = *(const float2*)&su.a.E1[warp][(j0 & 255)];
        float2 e18 = *(const float2*)&su.a.E1[warp][((j0 + 8) & 255)];
        float2 e20 = *(const float2*)&su.a.E2[warp][(j0 & 255)];
        float2 e28 = *(const float2*)&su.a.E2[warp][((j0 + 8) & 255)];

        uint32_t ah[2][4];
        ah[0][0] = build_a(c0a.x, c0a.y, e10.x, e10.y, e20.x, e20.y, Ai0, Bi0, th0);
        ah[0][1] = build_a(c1a.x, c1a.y, e10.x, e10.y, e20.x, e20.y, Ai1, Bi1, th1);
        ah[0][2] = build_a(c0b.x, c0b.y, e18.x, e18.y, e28.x, e28.y, Ai0, Bi0, th0);
        ah[0][3] = build_a(c1b.x, c1b.y, e18.x, e18.y, e28.x, e28.y, Ai1, Bi1, th1);
        ah[1][0] = build_a(c2a.x, c2a.y, e10.x, e10.y, e20.x, e20.y, Ai2, Bi2, th2);
        ah[1][1] = build_a(c3a.x, c3a.y, e10.x, e10.y, e20.x, e20.y, Ai3, Bi3, th3);
        ah[1][2] = build_a(c2b.x, c2b.y, e18.x, e18.y, e28.x, e28.y, Ai2, Bi2, th2);
        ah[1][3] = build_a(c3b.x, c3b.y, e18.x, e18.y, e28.x, e28.y, Ai3, Bi3, th3);

        if (kt < 13) {
            int ktn = kt + 3;
#pragma unroll
            for (int q = 0; q < 4; q++) {
                int row = cp_row + q * 8;
                unsigned daddr = (unsigned)__cvta_generic_to_shared(
                    &su.a.adjt[warp][kt % 3][row * 20 + cp_part * 4]);
                const int* src = adjw + (size_t)row * NV + ktn * 16 + cp_part * 4;
                asm volatile("cp.async.cg.shared.global [%0], [%1], 16;"
                             :: "r"(daddr), "l"(src) : "memory");
            }
            asm volatile("cp.async.commit_group;" ::: "memory");
        }

#pragma unroll
        for (int n = 0; n < 8; n++) {
#pragma unroll
            for (int m = 0; m < 2; m++) {
                MMA_F16(acc[m][n][0], acc[m][n][1], acc[m][n][2], acc[m][n][3],
                        ah[m][0], ah[m][1], ah[m][2], ah[m][3], b0[n], b1[n]);
            }
        }
    }

    // ---- cross-warp reduction ----
    __syncthreads();
    float* sw = &su.red[warp][0][0];
#pragma unroll
    for (int n = 0; n < 8; n++) {
        int c = n * 8 + tg * 2;
        *(float2*)&sw[gid * 68 + c]        = make_float2(acc[0][n][0], acc[0][n][1]);
        *(float2*)&sw[(gid + 8) * 68 + c]  = make_float2(acc[0][n][2], acc[0][n][3]);
        *(float2*)&sw[(gid + 16) * 68 + c] = make_float2(acc[1][n][0], acc[1][n][1]);
        *(float2*)&sw[(gid + 24) * 68 + c] = make_float2(acc[1][n][2], acc[1][n][3]);
    }
    __syncthreads();

    float* dst = g_part[jseg];
#pragma unroll
    for (int q = 0; q < 4; q++) {
        int v = tid + q * 128;
        int row = v >> 4;
        int col = (v & 15) * 4;
        float4 s0 = *(const float4*)&su.red[0][row][col];
        float4 s1 = *(const float4*)&su.red[1][row][col];
        float4 s2 = *(const float4*)&su.red[2][row][col];
        float4 s3 = *(const float4*)&su.red[3][row][col];
        float4 r;
        r.x = s0.x + s1.x + s2.x + s3.x;
        r.y = s0.y + s1.y + s2.y + s3.y;
        r.z = s0.z + s1.z + s2.z + s3.z;
        r.w = s0.w + s1.w + s2.w + s3.w;
        *(float4*)&dst[(size_t)(base + row) * 64 + col] = r;
    }

    // ---- fused final pass: last jseg CTA of this rb does dinv + ELU ----
    __threadfence();
    __syncthreads();
    if (tid == 0) {
        int old = atomicAdd(&g_cnt[rb], 1);
        s_last = (old == 3);
    }
    __syncthreads();
    if (s_last) {
        __threadfence();
#pragma unroll
        for (int q = 0; q < 4; q++) {
            int v = tid + q * 128;
            int row = v >> 4;
            int col = (v & 15) * 4;
            size_t off = (size_t)(base + row) * 64 + col;
            float4 s = *(const float4*)&g_part[0][off];
            float4 t1 = *(const float4*)&g_part[1][off];
            float4 t2 = *(const float4*)&g_part[2][off];
            float4 t3 = *(const float4*)&g_part[3][off];
            s.x += t1.x + t2.x + t3.x;
            s.y += t1.y + t2.y + t3.y;
            s.z += t1.z + t2.z + t3.z;
            s.w += t1.w + t2.w + t3.w;
            float di = g_dinv[base + row];
            s.x *= di; s.y *= di; s.z *= di; s.w *= di;
            s.x = s.x > 0.f ? s.x : (__expf(s.x) - 1.f);
            s.y = s.y > 0.f ? s.y : (__expf(s.y) - 1.f);
            s.z = s.z > 0.f ? s.z : (__expf(s.z) - 1.f);
            s.w = s.w > 0.f ? s.w : (__expf(s.w) - 1.f);
            *(float4*)&out[off] = s;
        }
    }
}

// ---------------- launch ----------------
extern "C" void kernel_launch(void* const* d_in, const int* in_sizes, int n_in,
                              void* d_out, int out_size) {
    const float* H = (const float*)d_in[0];
    const int* adj = (const int*)d_in[1];
    const float* W = (const float*)d_in[2];
    const float* a = (const float*)d_in[3];
    float* out = (float*)d_out;

    k1_wh<<<256, 256>>>(H, W, a);
    k2_denom<<<512, 256>>>();
    k3_main<<<512, 128>>>(adj, out);
}

// round 16
// speedup vs baseline: 1.7904x; 1.0147x over previous
#include <cuda_runtime.h>
#include <cuda_fp16.h>
#include <cstdint>

#define NV 4096
#define ALPHA 0.2f

// ---------------- device scratch ----------------
__device__ float g_e1[NV], g_e2[NV];
__device__ float g_E1[NV], g_E2[NV];
__device__ float g_A[NV], g_B[NV], g_thE[NV], g_dinv[NV];
__device__ float g_part[4][NV * 64];
// fragment-ordered B: [jt 0..255][n 0..7][reg 0..1][lane 0..31], u32 = f16x2
__device__ uint32_t g_WhB[256 * 512];
__device__ int g_cnt[128];

// ---------------- K1: Wh = H@W + e1/e2 + E1/E2 + fragment emit ---------------
// Block = 16 rows = one j-tile. 2 W-chunks of 128 k, 4-way acc split.
__global__ __launch_bounds__(256) void k1_wh(const float* __restrict__ H,
                                             const float* __restrict__ W,
                                             const float* __restrict__ a) {
    __shared__ float Ws[128][64];     // 32 KB
    __shared__ float Hs[16][132];     // 8.25 KB
    __shared__ float t[16][68];       // 4.25 KB
    int tid = threadIdx.x;
    int tr = tid >> 4;
    int tc = tid & 15;
    int row0 = blockIdx.x * 16;

    unsigned long long acc[4][2];
#pragma unroll
    for (int p = 0; p < 4; p++) { acc[p][0] = 0ull; acc[p][1] = 0ull; }

#pragma unroll
    for (int kk = 0; kk < 256; kk += 128) {
        // stage W chunk: 128x64 = 2048 float4, 8 per thread
#pragma unroll
        for (int q = 0; q < 8; q++) {
            int u = tid + q * 256;
            int r = u >> 4, c4 = u & 15;
            *(float4*)&Ws[r][c4 * 4] = *(const float4*)&W[(size_t)(kk + r) * 64 + c4 * 4];
        }
        // stage H chunk: 16x128 = 512 float4, 2 per thread
#pragma unroll
        for (int q = 0; q < 2; q++) {
            int u = tid + q * 256;
            int r = u >> 5, c4 = u & 31;
            *(float4*)&Hs[r][c4 * 4] = *(const float4*)&H[(size_t)(row0 + r) * 256 + kk + c4 * 4];
        }
        __syncthreads();
#pragma unroll 8
        for (int k = 0; k < 128; k++) {
            float4 w4 = *(const float4*)&Ws[k][tc * 4];
            unsigned long long w01, w23, hp;
            asm("mov.b64 %0, {%1, %2};" : "=l"(w01) : "f"(w4.x), "f"(w4.y));
            asm("mov.b64 %0, {%1, %2};" : "=l"(w23) : "f"(w4.z), "f"(w4.w));
            float h = Hs[tr][k];
            asm("mov.b64 %0, {%1, %1};" : "=l"(hp) : "f"(h));
            int p = k & 3;
            asm("fma.rn.f32x2 %0, %1, %2, %0;" : "+l"(acc[p][0]) : "l"(hp), "l"(w01));
            asm("fma.rn.f32x2 %0, %1, %2, %0;" : "+l"(acc[p][1]) : "l"(hp), "l"(w23));
        }
        __syncthreads();
    }

    // combine 4 phases
    float v0 = 0.f, v1 = 0.f, v2 = 0.f, v3 = 0.f;
#pragma unroll
    for (int p = 0; p < 4; p++) {
        v0 += __uint_as_float((uint32_t)acc[p][0]);
        v1 += __uint_as_float((uint32_t)(acc[p][0] >> 32));
        v2 += __uint_as_float((uint32_t)acc[p][1]);
        v3 += __uint_as_float((uint32_t)(acc[p][1] >> 32));
    }

    // stage Wh tile for fragment emission
    *(float4*)&t[tr][tc * 4] = make_float4(v0, v1, v2, v3);

    int i = row0 + tr;
    float p1 = v0 * __ldg(&a[tc * 4]) + v1 * __ldg(&a[tc * 4 + 1])
             + v2 * __ldg(&a[tc * 4 + 2]) + v3 * __ldg(&a[tc * 4 + 3]);
    float p2 = v0 * __ldg(&a[64 + tc * 4]) + v1 * __ldg(&a[64 + tc * 4 + 1])
             + v2 * __ldg(&a[64 + tc * 4 + 2]) + v3 * __ldg(&a[64 + tc * 4 + 3]);
#pragma unroll
    for (int off = 1; off < 16; off <<= 1) {
        p1 += __shfl_xor_sync(0xffffffffu, p1, off);
        p2 += __shfl_xor_sync(0xffffffffu, p2, off);
    }
    if (tc == 0) {
        g_e1[i] = p1;
        g_e2[i] = p2;
        g_E1[i] = __expf(p2);
        g_E2[i] = __expf(ALPHA * p2);
    }
    __syncthreads();

    // emit fp16 B fragments for this j-tile
    int jt = blockIdx.x;
#pragma unroll
    for (int q = 0; q < 2; q++) {
        int idx = tid + q * 256;          // 0..511
        int lane = idx & 31;
        int reg = (idx >> 5) & 1;
        int n = idx >> 6;
        int gid2 = lane >> 2, tg2 = lane & 3;
        int jr = tg2 * 2 + reg * 8;
        int c = n * 8 + gid2;
        __half2 h = __floats2half2_rn(t[jr][c], t[jr + 1][c]);
        g_WhB[(size_t)jt * 512 + idx] = *(uint32_t*)&h;
    }
}

// ---------------- K2: per-row denominator (+ counter reset) ----------------
__global__ __launch_bounds__(256) void k2_denom() {
    __shared__ float sE1[NV];
    __shared__ float sE2[NV];
    __shared__ float red[8];
    int tid = threadIdx.x;
    int warp = tid >> 5, lane = tid & 31;
    if (blockIdx.x < 128 && tid == 0) g_cnt[blockIdx.x] = 0;
#pragma unroll
    for (int t = 0; t < 4; t++) {
        ((float4*)sE1)[tid + t * 256] = __ldg(&((const float4*)g_E1)[tid + t * 256]);
        ((float4*)sE2)[tid + t * 256] = __ldg(&((const float4*)g_E2)[tid + t * 256]);
    }
    float mx = -1e30f;
#pragma unroll
    for (int t = 0; t < 4; t++) {
        float4 v = __ldg(&((const float4*)g_e2)[tid + t * 256]);
        mx = fmaxf(fmaxf(mx, v.x), fmaxf(fmaxf(v.y, v.z), v.w));
    }
#pragma unroll
    for (int o = 16; o > 0; o >>= 1) mx = fmaxf(mx, __shfl_xor_sync(0xffffffffu, mx, o));
    if (lane == 0) red[warp] = mx;
    __syncthreads();
    float e2max = red[0];
#pragma unroll
    for (int w = 1; w < 8; w++) e2max = fmaxf(e2max, red[w]);

    int i = blockIdx.x * 8 + warp;
    float e1v = g_e1[i];
    float s = e1v + e2max;
    float m = s > 0.f ? s : ALPHA * s;
    float A = __expf(e1v - m);
    float B = __expf(ALPHA * e1v - m);
    float thE = __expf(-e1v);

    float d = 0.f;
#pragma unroll 8
    for (int t = 0; t < 32; t++) {
        int j = (lane + t * 32) * 4;
        float4 E1v = *(const float4*)&sE1[j];
        float4 E2v = *(const float4*)&sE2[j];
        d += (E1v.x > thE) ? A * E1v.x : B * E2v.x;
        d += (E1v.y > thE) ? A * E1v.y : B * E2v.y;
        d += (E1v.z > thE) ? A * E1v.z : B * E2v.z;
        d += (E1v.w > thE) ? A * E1v.w : B * E2v.w;
    }
#pragma unroll
    for (int o = 16; o > 0; o >>= 1) d += __shfl_xor_sync(0xffffffffu, d, o);
    if (lane == 0) {
        g_A[i] = A; g_B[i] = B; g_thE[i] = thE;
        g_dinv[i] = 1.f / d;
    }
}

// ---------------- A-fragment build ----------------
__device__ __forceinline__ uint32_t build_a(int ax, int ay,
                                            float e1x, float e1y,
                                            float e2x, float e2y,
                                            float Ai, float Bi, float th) {
    float w0 = (ax > 0) ? ((e1x > th) ? Ai * e1x : Bi * e2x) : 0.f;
    float w1 = (ay > 0) ? ((e1y > th) ? Ai * e1y : Bi * e2y) : 0.f;
    __half2 h = __floats2half2_rn(w0, w1);
    return *(uint32_t*)&h;
}

#define MMA_F16(c0, c1, c2, c3, a0, a1, a2, a3, b0, b1)                         \
    asm("mma.sync.aligned.m16n8k16.row.col.f32.f16.f16.f32 "                   \
        "{%0,%1,%2,%3}, {%4,%5,%6,%7}, {%8,%9}, {%0,%1,%2,%3};"                \
        : "+f"(c0), "+f"(c1), "+f"(c2), "+f"(c3)                               \
        : "r"(a0), "r"(a1), "r"(a2), "r"(a3), "r"(b0), "r"(b1))

#define CP_WAIT(n) asm volatile("cp.async.wait_group %0;" :: "n"(n) : "memory")

// ---------------- K3: masked GEMM + fused final reduce/ELU -------------------
__global__ __launch_bounds__(128, 4) void k3_main(const int* __restrict__ adj,
                                                  float* __restrict__ out) {
    __shared__ union {
        struct {
            int adjt[4][3][640];
            float E1[4][256];
            float E2[4][256];
        } a;
        float red[4][32][68];
    } su;
    __shared__ int s_last;

    int tid = threadIdx.x;
    int warp = tid >> 5, lane = tid & 31;
    int gid = lane >> 2, tg = lane & 3;
    int rb = blockIdx.x >> 2;
    int jseg = blockIdx.x & 3;
    int jq = jseg * 1024 + warp * 256;
    int base = rb * 32;

    const int* adjw = adj + (size_t)base * NV + jq;
    int cp_row = lane >> 2;
    int cp_part = lane & 3;

    // prologue: adj tiles 0..2
#pragma unroll
    for (int kt = 0; kt < 3; kt++) {
#pragma unroll
        for (int q = 0; q < 4; q++) {
            int row = cp_row + q * 8;
            unsigned daddr = (unsigned)__cvta_generic_to_shared(
                &su.a.adjt[warp][kt][row * 20 + cp_part * 4]);
            const int* src = adjw + (size_t)row * NV + kt * 16 + cp_part * 4;
            asm volatile("cp.async.cg.shared.global [%0], [%1], 16;"
                         :: "r"(daddr), "l"(src) : "memory");
        }
        asm volatile("cp.async.commit_group;" ::: "memory");
    }

    // stage E for this warp's quarter
#pragma unroll
    for (int t = 0; t < 2; t++) {
        int idx = lane + t * 32;
        float4 v1 = __ldg(&((const float4*)(g_E1 + jq))[idx]);
        *(float4*)&su.a.E1[warp][idx * 4] = v1;
        float4 v2 = __ldg(&((const float4*)(g_E2 + jq))[idx]);
        *(float4*)&su.a.E2[warp][idx * 4] = v2;
    }
    __syncwarp();

    int r0 = base + gid, r1 = r0 + 8, r2 = r0 + 16, r3 = r0 + 24;
    float Ai0 = __ldg(&g_A[r0]), Bi0 = __ldg(&g_B[r0]), th0 = __ldg(&g_thE[r0]);
    float Ai1 = __ldg(&g_A[r1]), Bi1 = __ldg(&g_B[r1]), th1 = __ldg(&g_thE[r1]);
    float Ai2 = __ldg(&g_A[r2]), Bi2 = __ldg(&g_B[r2]), th2 = __ldg(&g_thE[r2]);
    float Ai3 = __ldg(&g_A[r3]), Bi3 = __ldg(&g_B[r3]), th3 = __ldg(&g_thE[r3]);

    float acc[2][8][4];
#pragma unroll
    for (int m = 0; m < 2; m++)
#pragma unroll
        for (int n = 0; n < 8; n++)
#pragma unroll
            for (int q = 0; q < 4; q++) acc[m][n][q] = 0.f;

    int jt0 = jq >> 4;

#pragma unroll
    for (int kt = 0; kt < 16; ++kt) {
        uint32_t b0[8], b1[8];
        const uint32_t* bb = g_WhB + (size_t)(jt0 + kt) * 512 + lane;
#pragma unroll
        for (int n = 0; n < 8; n++) {
            b0[n] = __ldg(bb + n * 64);
            b1[n] = __ldg(bb + n * 64 + 32);
        }

        if (kt <= 13) { CP_WAIT(2); } else if (kt == 14) { CP_WAIT(1); } else { CP_WAIT(0); }
        __syncwarp();

        const int* sa = su.a.adjt[warp][kt % 3];
        int2 c0a = *(const int2*)&sa[gid * 20 + tg * 2];
        int2 c0b = *(const int2*)&sa[gid * 20 + tg * 2 + 8];
        int2 c1a = *(const int2*)&sa[(gid + 8) * 20 + tg * 2];
        int2 c1b = *(const int2*)&sa[(gid + 8) * 20 + tg * 2 + 8];
        int2 c2a = *(const int2*)&sa[(gid + 16) * 20 + tg * 2];
        int2 c2b = *(const int2*)&sa[(gid + 16) * 20 + tg * 2 + 8];
        int2 c3a = *(const int2*)&sa[(gid + 24) * 20 + tg * 2];
        int2 c3b = *(const int2*)&sa[(gid + 24) * 20 + tg * 2 + 8];

        int j0 = kt * 16 + tg * 2;
        float2 e10 = *(const float2*)&su.a.E1[warp][(j0 & 255)];
        float2 e18 = *(const float2*)&su.a.E1[warp][((j0 + 8) & 255)];
        float2 e20 = *(const float2*)&su.a.E2[warp][(j0 & 255)];
        float2 e28 = *(const float2*)&su.a.E2[warp][((j0 + 8) & 255)];

        uint32_t ah[2][4];
        ah[0][0] = build_a(c0a.x, c0a.y, e10.x, e10.y, e20.x, e20.y, Ai0, Bi0, th0);
        ah[0][1] = build_a(c1a.x, c1a.y, e10.x, e10.y, e20.x, e20.y, Ai1, Bi1, th1);
        ah[0][2] = build_a(c0b.x, c0b.y, e18.x, e18.y, e28.x, e28.y, Ai0, Bi0, th0);
        ah[0][3] = build_a(c1b.x, c1b.y, e18.x, e18.y, e28.x, e28.y, Ai1, Bi1, th1);
        ah[1][0] = build_a(c2a.x, c2a.y, e10.x, e10.y, e20.x, e20.y, Ai2, Bi2, th2);
        ah[1][1] = build_a(c3a.x, c3a.y, e10.x, e10.y, e20.x, e20.y, Ai3, Bi3, th3);
        ah[1][2] = build_a(c2b.x, c2b.y, e18.x, e18.y, e28.x, e28.y, Ai2, Bi2, th2);
        ah[1][3] = build_a(c3b.x, c3b.y, e18.x, e18.y, e28.x, e28.y, Ai3, Bi3, th3);

        if (kt < 13) {
            int ktn = kt + 3;
#pragma unroll
            for (int q = 0; q < 4; q++) {
                int row = cp_row + q * 8;
                unsigned daddr = (unsigned)__cvta_generic_to_shared(
                    &su.a.adjt[warp][kt % 3][row * 20 + cp_part * 4]);
                const int* src = adjw + (size_t)row * NV + ktn * 16 + cp_part * 4;
                asm volatile("cp.async.cg.shared.global [%0], [%1], 16;"
                             :: "r"(daddr), "l"(src) : "memory");
            }
            asm volatile("cp.async.commit_group;" ::: "memory");
        }

#pragma unroll
        for (int n = 0; n < 8; n++) {
#pragma unroll
            for (int m = 0; m < 2; m++) {
                MMA_F16(acc[m][n][0], acc[m][n][1], acc[m][n][2], acc[m][n][3],
                        ah[m][0], ah[m][1], ah[m][2], ah[m][3], b0[n], b1[n]);
            }
        }
    }

    // ---- cross-warp reduction ----
    __syncthreads();
    float* sw = &su.red[warp][0][0];
#pragma unroll
    for (int n = 0; n < 8; n++) {
        int c = n * 8 + tg * 2;
        *(float2*)&sw[gid * 68 + c]        = make_float2(acc[0][n][0], acc[0][n][1]);
        *(float2*)&sw[(gid + 8) * 68 + c]  = make_float2(acc[0][n][2], acc[0][n][3]);
        *(float2*)&sw[(gid + 16) * 68 + c] = make_float2(acc[1][n][0], acc[1][n][1]);
        *(float2*)&sw[(gid + 24) * 68 + c] = make_float2(acc[1][n][2], acc[1][n][3]);
    }
    __syncthreads();

    float* dst = g_part[jseg];
#pragma unroll
    for (int q = 0; q < 4; q++) {
        int v = tid + q * 128;
        int row = v >> 4;
        int col = (v & 15) * 4;
        float4 s0 = *(const float4*)&su.red[0][row][col];
        float4 s1 = *(const float4*)&su.red[1][row][col];
        float4 s2 = *(const float4*)&su.red[2][row][col];
        float4 s3 = *(const float4*)&su.red[3][row][col];
        float4 r;
        r.x = s0.x + s1.x + s2.x + s3.x;
        r.y = s0.y + s1.y + s2.y + s3.y;
        r.z = s0.z + s1.z + s2.z + s3.z;
        r.w = s0.w + s1.w + s2.w + s3.w;
        *(float4*)&dst[(size_t)(base + row) * 64 + col] = r;
    }

    // ---- fused final pass: last jseg CTA of this rb does dinv + ELU ----
    __threadfence();
    __syncthreads();
    if (tid == 0) {
        int old = atomicAdd(&g_cnt[rb], 1);
        s_last = (old == 3);
    }
    __syncthreads();
    if (s_last) {
        __threadfence();
#pragma unroll
        for (int q = 0; q < 4; q++) {
            int v = tid + q * 128;
            int row = v >> 4;
            int col = (v & 15) * 4;
            size_t off = (size_t)(base + row) * 64 + col;
            float4 s = *(const float4*)&g_part[0][off];
            float4 t1 = *(const float4*)&g_part[1][off];
            float4 t2 = *(const float4*)&g_part[2][off];
            float4 t3 = *(const float4*)&g_part[3][off];
            s.x += t1.x + t2.x + t3.x;
            s.y += t1.y + t2.y + t3.y;
            s.z += t1.z + t2.z + t3.z;
            s.w += t1.w + t2.w + t3.w;
            float di = g_dinv[base + row];
            s.x *= di; s.y *= di; s.z *= di; s.w *= di;
            s.x = s.x > 0.f ? s.x : (__expf(s.x) - 1.f);
            s.y = s.y > 0.f ? s.y : (__expf(s.y) - 1.f);
            s.z = s.z > 0.f ? s.z : (__expf(s.z) - 1.f);
            s.w = s.w > 0.f ? s.w : (__expf(s.w) - 1.f);
            *(float4*)&out[off] = s;
        }
    }
}

// ---------------- launch ----------------
extern "C" void kernel_launch(void* const* d_in, const int* in_sizes, int n_in,
                              void* d_out, int out_size) {
    const float* H = (const float*)d_in[0];
    const int* adj = (const int*)d_in[1];
    const float* W = (const float*)d_in[2];
    const float* a = (const float*)d_in[3];
    float* out = (float*)d_out;

    k1_wh<<<256, 256>>>(H, W, a);
    k2_denom<<<512, 256>>>();
    k3_main<<<512, 128>>>(adj, out);
}